// round 2
// baseline (speedup 1.0000x reference)
#include <cuda_runtime.h>
#include <cuda_bf16.h>
#include <math.h>

// ---------------- problem constants ----------------
#define BB   8
#define HH   96
#define WW   96
#define CC   128
#define TT   (BB*HH*WW)      // 73728 tokens
#define WS   8
#define NWIN 144             // 12*12 windows per image
#define WTOT (BB*NWIN)       // 1152 windows
#define HEADS 4
#define HD    32
#define NTOK  64             // tokens per window

// ---------------- scratch (device globals; no allocation) ----------------
__device__ float g_x[TT*CC];          // residual stream
__device__ float g_ln[TT*CC];         // LN output (window-ordered for ln1)
__device__ float g_big[TT*512];       // qkv (T x 384) / fc1-out (T x 512)
__device__ float g_attn[TT*CC];       // attention output (window-ordered)
__device__ float g_xc[(TT/4)*512];    // patch-merge concat + LN

// ---------------- helpers ----------------
__device__ __forceinline__ int win_to_token(int m, int shift) {
    // m: window-ordered row index -> natural token index (reverse roll)
    int b   = m / (NWIN*NTOK);
    int rem = m - b*(NWIN*NTOK);
    int win = rem >> 6;
    int n   = rem & 63;
    int wr = win / 12, wc = win - wr*12;
    int hp = wr*8 + (n >> 3);
    int wp = wc*8 + (n & 7);
    int h = hp + shift; if (h >= HH) h -= HH;
    int w = wp + shift; if (w >= WW) w -= WW;
    return b*(HH*WW) + h*WW + w;
}

// ---------------- LN (warp per token), optional roll+window gather ----------------
__global__ void __launch_bounds__(256) ln_kernel(
    const float* __restrict__ x, const float* __restrict__ g,
    const float* __restrict__ b, float* __restrict__ out,
    int shift, int windowed)
{
    int warp = threadIdx.x >> 5;
    int lane = threadIdx.x & 31;
    int token = blockIdx.x*8 + warp;
    const float4* row = (const float4*)(x + (size_t)token*CC);
    float4 v = row[lane];
    float s = v.x + v.y + v.z + v.w;
    #pragma unroll
    for (int o = 16; o > 0; o >>= 1) s += __shfl_xor_sync(0xffffffffu, s, o);
    float m = s * (1.0f/128.0f);
    float dx = v.x - m, dy = v.y - m, dz = v.z - m, dw = v.w - m;
    float q = dx*dx + dy*dy + dz*dz + dw*dw;
    #pragma unroll
    for (int o = 16; o > 0; o >>= 1) q += __shfl_xor_sync(0xffffffffu, q, o);
    float inv = rsqrtf(q * (1.0f/128.0f) + 1e-5f);
    float4 gg = ((const float4*)g)[lane];
    float4 bb = ((const float4*)b)[lane];
    float4 r;
    r.x = dx*inv*gg.x + bb.x;
    r.y = dy*inv*gg.y + bb.y;
    r.z = dz*inv*gg.z + bb.z;
    r.w = dw*inv*gg.w + bb.w;
    int dest = token;
    if (windowed) {
        int bi = token / (HH*WW);
        int hw = token - bi*(HH*WW);
        int h = hw / WW, w = hw - (hw/WW)*WW;
        int hp = h - shift; if (hp < 0) hp += HH;
        int wp = w - shift; if (wp < 0) wp += WW;
        dest = bi*(NWIN*NTOK) + ((hp>>3)*12 + (wp>>3))*NTOK + ((hp&7)*8 + (wp&7));
    }
    ((float4*)(out + (size_t)dest*CC))[lane] = r;
}

// ---------------- generic fp32 GEMM, 128x64x16 tile, fused epilogues ----------------
// MODE 0: qkv  (+bias, scale q cols by 1/sqrt(hd))
// MODE 1: proj (+bias, reverse-roll scatter, + residual from res) -> out natural order
// MODE 2: fc1  (+bias, exact GELU)
// MODE 3: fc2  (+bias, + residual from res, natural order)
// MODE 4: plain (no bias)
#define BMg 128
#define BNg 64
#define BKg 16
template<int MODE>
__global__ void __launch_bounds__(256) gemm_kernel(
    const float* __restrict__ A, const float* __restrict__ Bw,
    const float* __restrict__ bias, float* __restrict__ out,
    const float* __restrict__ res, int M, int N, int K, int shift)
{
    __shared__ float As[BKg][BMg];
    __shared__ float Bs[BKg][BNg];
    int tid = threadIdx.x;
    int tx = tid & 15, ty = tid >> 4;
    int m0 = blockIdx.y * BMg, n0 = blockIdx.x * BNg;

    float acc[8][4];
    #pragma unroll
    for (int i = 0; i < 8; i++)
        #pragma unroll
        for (int j = 0; j < 4; j++) acc[i][j] = 0.0f;

    int ar = tid >> 2, ac = (tid & 3) * 4;
    int br = tid >> 4, bc = (tid & 15) * 4;
    const float* Ap = A + (size_t)m0 * K;

    for (int kb = 0; kb < K; kb += BKg) {
        float4 a0 = *(const float4*)(Ap + (size_t)ar      * K + kb + ac);
        float4 a1 = *(const float4*)(Ap + (size_t)(ar+64) * K + kb + ac);
        float4 b0 = *(const float4*)(Bw + (size_t)(kb+br) * N + n0 + bc);
        As[ac+0][ar] = a0.x; As[ac+1][ar] = a0.y; As[ac+2][ar] = a0.z; As[ac+3][ar] = a0.w;
        As[ac+0][ar+64] = a1.x; As[ac+1][ar+64] = a1.y; As[ac+2][ar+64] = a1.z; As[ac+3][ar+64] = a1.w;
        *(float4*)&Bs[br][bc] = b0;
        __syncthreads();
        #pragma unroll
        for (int kk = 0; kk < BKg; kk++) {
            float4 av0 = *(const float4*)&As[kk][ty*8];
            float4 av1 = *(const float4*)&As[kk][ty*8+4];
            float4 bv  = *(const float4*)&Bs[kk][tx*4];
            float a[8] = {av0.x, av0.y, av0.z, av0.w, av1.x, av1.y, av1.z, av1.w};
            float bb[4] = {bv.x, bv.y, bv.z, bv.w};
            #pragma unroll
            for (int i = 0; i < 8; i++)
                #pragma unroll
                for (int j = 0; j < 4; j++) acc[i][j] += a[i]*bb[j];
        }
        __syncthreads();
    }

    int nbase = n0 + tx*4;
    float bres[4] = {0.f,0.f,0.f,0.f};
    if (MODE != 4) {
        bres[0] = bias[nbase+0]; bres[1] = bias[nbase+1];
        bres[2] = bias[nbase+2]; bres[3] = bias[nbase+3];
    }
    float qscale = 1.0f;
    if (MODE == 0 && n0 < 128) qscale = 0.17677669529663687f; // 32^-0.5

    #pragma unroll
    for (int i = 0; i < 8; i++) {
        int m = m0 + ty*8 + i;
        float v0 = acc[i][0] + bres[0];
        float v1 = acc[i][1] + bres[1];
        float v2 = acc[i][2] + bres[2];
        float v3 = acc[i][3] + bres[3];
        if (MODE == 0) {
            v0 *= qscale; v1 *= qscale; v2 *= qscale; v3 *= qscale;
            float4 o = {v0,v1,v2,v3};
            *(float4*)(out + (size_t)m*N + nbase) = o;
        } else if (MODE == 1) {
            int t = win_to_token(m, shift);
            const float4 rv = *(const float4*)(res + (size_t)t*CC + nbase);
            float4 o = {v0+rv.x, v1+rv.y, v2+rv.z, v3+rv.w};
            *(float4*)(out + (size_t)t*CC + nbase) = o;
        } else if (MODE == 2) {
            float4 o;
            o.x = 0.5f*v0*(1.0f + erff(v0*0.7071067811865476f));
            o.y = 0.5f*v1*(1.0f + erff(v1*0.7071067811865476f));
            o.z = 0.5f*v2*(1.0f + erff(v2*0.7071067811865476f));
            o.w = 0.5f*v3*(1.0f + erff(v3*0.7071067811865476f));
            *(float4*)(out + (size_t)m*N + nbase) = o;
        } else if (MODE == 3) {
            const float4 rv = *(const float4*)(res + (size_t)m*N + nbase);
            float4 o = {v0+rv.x, v1+rv.y, v2+rv.z, v3+rv.w};
            *(float4*)(out + (size_t)m*N + nbase) = o;
        } else {
            float4 o = {v0,v1,v2,v3};
            *(float4*)(out + (size_t)m*N + nbase) = o;
        }
    }
}

// ---------------- fused windowed attention: one (window, head) per block ----------------
__global__ void __launch_bounds__(128) attn_kernel(
    const float* __restrict__ qkv, float* __restrict__ out, int masked)
{
    __shared__ float qs[64][33];
    __shared__ float ks[64][32];
    __shared__ float vs[64][32];
    __shared__ float osm[64][32];
    __shared__ float red[2][64];
    __shared__ int lab[64];

    int tid = threadIdx.x;
    int win = blockIdx.x >> 2, head = blockIdx.x & 3;
    const float* base = qkv + (size_t)win*NTOK*384 + head*HD;

    for (int i = tid; i < 512; i += 128) {     // 64 rows x 8 float4
        int n = i >> 3, d4 = (i & 7) * 4;
        float4 q4 = *(const float4*)(base + (size_t)n*384 + d4);
        float4 k4 = *(const float4*)(base + (size_t)n*384 + 128 + d4);
        float4 v4 = *(const float4*)(base + (size_t)n*384 + 256 + d4);
        qs[n][d4+0] = q4.x; qs[n][d4+1] = q4.y; qs[n][d4+2] = q4.z; qs[n][d4+3] = q4.w;
        *(float4*)&ks[n][d4] = k4;
        *(float4*)&vs[n][d4] = v4;
    }
    if (masked && tid < 64) {
        int wloc = win % NWIN;
        int wr = wloc / 12, wc = wloc - wr*12;
        int hh = wr*8 + (tid >> 3), ww = wc*8 + (tid & 7);
        int rh = hh < 88 ? 0 : (hh < 92 ? 1 : 2);
        int rw = ww < 88 ? 0 : (ww < 92 ? 1 : 2);
        lab[tid] = rh*3 + rw;
    }
    __syncthreads();

    int r = tid & 63, ch = tid >> 6;   // thread owns row r, column half ch
    float qreg[32];
    #pragma unroll
    for (int k = 0; k < 32; k++) qreg[k] = qs[r][k];

    float sreg[32];
    #pragma unroll
    for (int cc = 0; cc < 32; cc++) {
        int c = ch*32 + cc;
        float s = 0.0f;
        #pragma unroll
        for (int k = 0; k < 32; k++) s += qreg[k]*ks[c][k];
        sreg[cc] = s;
    }
    if (masked) {
        int lr = lab[r];
        float ninf = __int_as_float(0xff800000);
        #pragma unroll
        for (int cc = 0; cc < 32; cc++)
            if (lab[ch*32+cc] != lr) sreg[cc] = ninf;
    }
    float mx = sreg[0];
    #pragma unroll
    for (int cc = 1; cc < 32; cc++) mx = fmaxf(mx, sreg[cc]);
    red[ch][r] = mx; __syncthreads();
    mx = fmaxf(red[0][r], red[1][r]);
    __syncthreads();
    float sum = 0.0f;
    #pragma unroll
    for (int cc = 0; cc < 32; cc++) { sreg[cc] = __expf(sreg[cc]-mx); sum += sreg[cc]; }
    red[ch][r] = sum; __syncthreads();
    float inv = 1.0f/(red[0][r] + red[1][r]);
    #pragma unroll
    for (int cc = 0; cc < 32; cc++) sreg[cc] *= inv;

    float o[32];
    #pragma unroll
    for (int d = 0; d < 32; d++) o[d] = 0.0f;
    #pragma unroll
    for (int cc = 0; cc < 32; cc++) {
        int c = ch*32 + cc;
        float p = sreg[cc];
        #pragma unroll
        for (int d = 0; d < 32; d++) o[d] += p*vs[c][d];
    }
    if (ch == 1) {
        #pragma unroll
        for (int d = 0; d < 32; d++) osm[r][d] = o[d];
    }
    __syncthreads();
    if (ch == 0) {
        #pragma unroll
        for (int d = 0; d < 32; d++) osm[r][d] += o[d];
    }
    __syncthreads();

    float* orow = out + (size_t)win*NTOK*CC + head*HD;
    for (int i = tid; i < 512; i += 128) {
        int n = i >> 3, d4 = (i & 7) * 4;
        *(float4*)(orow + (size_t)n*CC + d4) = *(float4*)&osm[n][d4];
    }
}

// ---------------- patch-merge gather + LN over 512 ----------------
__global__ void __launch_bounds__(128) merge_ln_kernel(
    const float* __restrict__ x, const float* __restrict__ g,
    const float* __restrict__ b, float* __restrict__ out)
{
    __shared__ float sred[8];
    int token = blockIdx.x;
    int b_ = token / 2304;
    int ij = token - b_*2304;
    int i2 = ij / 48, j2 = ij - (ij/48)*48;
    int tid = threadIdx.x;
    int warp = tid >> 5, lane = tid & 31;
    int chunk = tid >> 5;                 // 4 chunks of 128 channels
    int cc = (tid & 31) * 4;
    int dh = chunk & 1, dw = chunk >> 1;  // [x(2i,2j), x(2i+1,2j), x(2i,2j+1), x(2i+1,2j+1)]
    int h = 2*i2 + dh, w = 2*j2 + dw;
    const float* src = x + ((size_t)(b_*(HH*WW) + h*WW + w))*CC + cc;
    float4 v = *(const float4*)src;

    float s = v.x + v.y + v.z + v.w;
    #pragma unroll
    for (int o = 16; o > 0; o >>= 1) s += __shfl_xor_sync(0xffffffffu, s, o);
    if (lane == 0) sred[warp] = s;
    __syncthreads();
    float m = (sred[0]+sred[1]+sred[2]+sred[3]) * (1.0f/512.0f);

    float dx = v.x-m, dy = v.y-m, dz = v.z-m, dwv = v.w-m;
    float q = dx*dx + dy*dy + dz*dz + dwv*dwv;
    #pragma unroll
    for (int o = 16; o > 0; o >>= 1) q += __shfl_xor_sync(0xffffffffu, q, o);
    if (lane == 0) sred[4+warp] = q;
    __syncthreads();
    float var = (sred[4]+sred[5]+sred[6]+sred[7]) * (1.0f/512.0f);
    float inv = rsqrtf(var + 1e-5f);

    int oc = tid*4;
    float4 gg = *(const float4*)(g + oc);
    float4 bb = *(const float4*)(b + oc);
    float4 r;
    r.x = dx*inv*gg.x + bb.x;
    r.y = dy*inv*gg.y + bb.y;
    r.z = dz*inv*gg.z + bb.z;
    r.w = dwv*inv*gg.w + bb.w;
    *(float4*)(out + (size_t)token*512 + oc) = r;
}

// ---------------- host orchestration ----------------
extern "C" void kernel_launch(void* const* d_in, const int* in_sizes, int n_in,
                              void* d_out, int out_size)
{
    (void)in_sizes; (void)n_in; (void)out_size;
    const float* x_in = (const float*)d_in[0];
    // parameter pointers: a_* = 1..12, b_* = 13..24
    const float* P[32];
    for (int i = 0; i < 28; i++) P[i] = (const float*)d_in[i];
    const float* mln_g = (const float*)d_in[25];
    const float* mln_b = (const float*)d_in[26];
    const float* red_w = (const float*)d_in[27];

    float *px, *pln, *pbig, *pattn, *pxc;
    cudaGetSymbolAddress((void**)&px,   g_x);
    cudaGetSymbolAddress((void**)&pln,  g_ln);
    cudaGetSymbolAddress((void**)&pbig, g_big);
    cudaGetSymbolAddress((void**)&pattn,g_attn);
    cudaGetSymbolAddress((void**)&pxc,  g_xc);

    cudaMemcpyAsync(px, x_in, (size_t)TT*CC*sizeof(float), cudaMemcpyDeviceToDevice);

    for (int blk = 0; blk < 2; blk++) {
        int base = 1 + blk*12;
        const float* ln1_g  = P[base+0];
        const float* ln1_b  = P[base+1];
        const float* qkv_w  = P[base+2];
        const float* qkv_b  = P[base+3];
        const float* proj_w = P[base+4];
        const float* proj_b = P[base+5];
        const float* ln2_g  = P[base+6];
        const float* ln2_b  = P[base+7];
        const float* fc1_w  = P[base+8];
        const float* fc1_b  = P[base+9];
        const float* fc2_w  = P[base+10];
        const float* fc2_b  = P[base+11];
        int shift  = (blk == 0) ? 0 : 4;
        int masked = (blk == 0) ? 0 : 1;

        ln_kernel<<<TT/8, 256>>>(px, ln1_g, ln1_b, pln, shift, 1);
        gemm_kernel<0><<<dim3(384/BNg, TT/BMg), 256>>>(pln, qkv_w, qkv_b, pbig, nullptr, TT, 384, 128, 0);
        attn_kernel<<<WTOT*HEADS, 128>>>(pbig, pattn, masked);
        gemm_kernel<1><<<dim3(128/BNg, TT/BMg), 256>>>(pattn, proj_w, proj_b, px, px, TT, 128, 128, shift);
        ln_kernel<<<TT/8, 256>>>(px, ln2_g, ln2_b, pln, 0, 0);
        gemm_kernel<2><<<dim3(512/BNg, TT/BMg), 256>>>(pln, fc1_w, fc1_b, pbig, nullptr, TT, 512, 128, 0);
        gemm_kernel<3><<<dim3(128/BNg, TT/BMg), 256>>>(pbig, fc2_w, fc2_b, px, px, TT, 128, 512, 0);
    }

    merge_ln_kernel<<<TT/4, 128>>>(px, mln_g, mln_b, pxc);
    gemm_kernel<4><<<dim3(256/BNg, (TT/4)/BMg), 256>>>(pxc, red_w, nullptr, (float*)d_out, nullptr, TT/4, 256, 512, 0);
}

// round 5
// speedup vs baseline: 2.0562x; 2.0562x over previous
#include <cuda_runtime.h>
#include <cuda_bf16.h>
#include <math.h>
#include <stdint.h>

// ---------------- problem constants ----------------
#define BB   8
#define HH   96
#define WW   96
#define CC   128
#define TT   (BB*HH*WW)      // 73728 tokens
#define NWIN 144             // 12*12 windows per image
#define WTOT (BB*NWIN)       // 1152 windows
#define NTOK 64              // tokens per window

// ---------------- scratch (device globals; no allocation) ----------------
__device__ float g_x[TT*CC];          // residual stream
__device__ float g_ln[TT*CC];         // LN output (window-ordered for ln1)
__device__ float g_big[TT*512];       // qkv (T x 384) / fc1-out (T x 512)
__device__ float g_attn[TT*CC];       // attention output (window-ordered)
__device__ float g_xc[(TT/4)*512];    // patch-merge concat + LN

// ---------------- helpers ----------------
__device__ __forceinline__ uint32_t smem_u32(const void* p) {
    uint32_t a;
    asm("{ .reg .u64 t; cvta.to.shared.u64 t, %1; cvt.u32.u64 %0, t; }" : "=r"(a) : "l"(p));
    return a;
}
__device__ __forceinline__ void cp16(uint32_t dst, const void* src) {
    asm volatile("cp.async.cg.shared.global [%0], [%1], 16;" :: "r"(dst), "l"(src));
}
__device__ __forceinline__ void cp_commit() {
    asm volatile("cp.async.commit_group;" ::: "memory");
}
template<int N>
__device__ __forceinline__ void cp_wait() {
    asm volatile("cp.async.wait_group %0;" :: "n"(N) : "memory");
}
__device__ __forceinline__ void mma_tf32(float* c, const uint32_t* a, const uint32_t* b) {
    asm volatile(
        "mma.sync.aligned.m16n8k8.row.col.f32.tf32.tf32.f32 "
        "{%0,%1,%2,%3}, {%4,%5,%6,%7}, {%8,%9}, {%0,%1,%2,%3};"
        : "+f"(c[0]), "+f"(c[1]), "+f"(c[2]), "+f"(c[3])
        : "r"(a[0]), "r"(a[1]), "r"(a[2]), "r"(a[3]), "r"(b[0]), "r"(b[1]));
}

__device__ __forceinline__ int win_to_token(int m, int shift) {
    int b   = m / (NWIN*NTOK);
    int rem = m - b*(NWIN*NTOK);
    int win = rem >> 6;
    int n   = rem & 63;
    int wr = win / 12, wc = win - wr*12;
    int hp = wr*8 + (n >> 3);
    int wp = wc*8 + (n & 7);
    int h = hp + shift; if (h >= HH) h -= HH;
    int w = wp + shift; if (w >= WW) w -= WW;
    return b*(HH*WW) + h*WW + w;
}

// ---------------- LN (warp per token), optional roll+window gather ----------------
__global__ void __launch_bounds__(256) ln_kernel(
    const float* __restrict__ x, const float* __restrict__ g,
    const float* __restrict__ b, float* __restrict__ out,
    int shift, int windowed)
{
    int warp = threadIdx.x >> 5;
    int lane = threadIdx.x & 31;
    int token = blockIdx.x*8 + warp;
    const float4* row = (const float4*)(x + (size_t)token*CC);
    float4 v = row[lane];
    float s = v.x + v.y + v.z + v.w;
    #pragma unroll
    for (int o = 16; o > 0; o >>= 1) s += __shfl_xor_sync(0xffffffffu, s, o);
    float m = s * (1.0f/128.0f);
    float dx = v.x - m, dy = v.y - m, dz = v.z - m, dw = v.w - m;
    float q = dx*dx + dy*dy + dz*dz + dw*dw;
    #pragma unroll
    for (int o = 16; o > 0; o >>= 1) q += __shfl_xor_sync(0xffffffffu, q, o);
    float inv = rsqrtf(q * (1.0f/128.0f) + 1e-5f);
    float4 gg = ((const float4*)g)[lane];
    float4 bb = ((const float4*)b)[lane];
    float4 r;
    r.x = dx*inv*gg.x + bb.x;
    r.y = dy*inv*gg.y + bb.y;
    r.z = dz*inv*gg.z + bb.z;
    r.w = dw*inv*gg.w + bb.w;
    int dest = token;
    if (windowed) {
        int bi = token / (HH*WW);
        int hw = token - bi*(HH*WW);
        int h = hw / WW, w = hw - (hw/WW)*WW;
        int hp = h - shift; if (hp < 0) hp += HH;
        int wp = w - shift; if (wp < 0) wp += WW;
        dest = bi*(NWIN*NTOK) + ((hp>>3)*12 + (wp>>3))*NTOK + ((hp&7)*8 + (wp&7));
    }
    ((float4*)(out + (size_t)dest*CC))[lane] = r;
}

// ---------------- mma.sync tf32 GEMM: D[M,N] = A[M,K] @ B[K,N], fused epilogues ----------------
// MODE 0: qkv  (+bias, qscale on n0==0 tile)
// MODE 1: proj (+bias, reverse-roll scatter + residual)
// MODE 2: fc1  (+bias, exact GELU)
// MODE 3: fc2  (+bias, + residual)
// MODE 4: plain
#define GBM 128
#define GBN 128
#define GBK 32
#define ASTR 36                 // A smem row stride (floats)
#define BSTR 132                // B smem row stride (floats)
#define AFLT (GBM*ASTR)         // 4608 floats
#define BFLT (GBK*BSTR)         // 4224 floats
#define BUFFLT (AFLT+BFLT)      // 8832 floats
#define GSMEM (2*BUFFLT*4)      // 70656 bytes

template<int MODE>
__global__ void __launch_bounds__(256) tgemm(
    const float* __restrict__ A, const float* __restrict__ Bw,
    const float* __restrict__ bias, float* __restrict__ out,
    const float* __restrict__ res, int M, int N, int K, int shift)
{
    extern __shared__ float sm[];
    uint32_t sb = smem_u32(sm);
    int tid = threadIdx.x;
    int wid = tid >> 5;
    int lane = tid & 31;
    int g = lane >> 2, q = lane & 3;
    int warp_m = wid >> 2, warp_n = wid & 3;  // 2 x 4
    int m0 = blockIdx.y * GBM, n0 = blockIdx.x * GBN;

    const float* Ab = A + (size_t)m0 * K;

    // loader indices
    int arow = tid >> 3, ac4 = (tid & 7) * 4;        // A: +row stride per 32 rows of float4s? (1024 f4, 4 iters)
    int brow = tid >> 5, bc4 = (tid & 31) * 4;       // B: 1024 f4, 4 iters

    float c[4][4][4];
    #pragma unroll
    for (int mt = 0; mt < 4; mt++)
        #pragma unroll
        for (int nt = 0; nt < 4; nt++)
            #pragma unroll
            for (int i = 0; i < 4; i++) c[mt][nt][i] = 0.0f;

    int NC = K / GBK;

    // ---- load tile kb into buffer (kb&1) ----
    auto load_tile = [&](int kb) {
        int buf = kb & 1;
        uint32_t sA = sb + buf*(BUFFLT*4);
        uint32_t sB = sA + AFLT*4;
        const float* Ap = Ab + kb*GBK;
        const float* Bp = Bw + (size_t)(kb*GBK)*N + n0;
        #pragma unroll
        for (int i = 0; i < 4; i++) {
            int r = arow + i*32;
            cp16(sA + (uint32_t)(r*ASTR + ac4)*4, Ap + (size_t)r*K + ac4);
        }
        #pragma unroll
        for (int i = 0; i < 4; i++) {
            int r = brow + i*8;
            cp16(sB + (uint32_t)(r*BSTR + bc4)*4, Bp + (size_t)r*N + bc4);
        }
        cp_commit();
    };

    load_tile(0);

    for (int kb = 0; kb < NC; kb++) {
        if (kb + 1 < NC) {
            load_tile(kb + 1);
            cp_wait<1>();
        } else {
            cp_wait<0>();
        }
        __syncthreads();

        const float* As_ = sm + (kb & 1)*BUFFLT;
        const float* Bs_ = As_ + AFLT;

        #pragma unroll
        for (int ks = 0; ks < 4; ks++) {
            int k = ks*8;
            uint32_t a[4][4], b[4][2];
            #pragma unroll
            for (int mt = 0; mt < 4; mt++) {
                int r0 = warp_m*64 + mt*16 + g;
                a[mt][0] = __float_as_uint(As_[r0*ASTR + k + q]);
                a[mt][1] = __float_as_uint(As_[(r0+8)*ASTR + k + q]);
                a[mt][2] = __float_as_uint(As_[r0*ASTR + k + q + 4]);
                a[mt][3] = __float_as_uint(As_[(r0+8)*ASTR + k + q + 4]);
            }
            #pragma unroll
            for (int nt = 0; nt < 4; nt++) {
                int col = warp_n*32 + nt*8 + g;
                b[nt][0] = __float_as_uint(Bs_[(k+q)*BSTR + col]);
                b[nt][1] = __float_as_uint(Bs_[(k+q+4)*BSTR + col]);
            }
            #pragma unroll
            for (int mt = 0; mt < 4; mt++)
                #pragma unroll
                for (int nt = 0; nt < 4; nt++)
                    mma_tf32(c[mt][nt], a[mt], b[nt]);
        }
        __syncthreads();
    }

    // ---- epilogue ----
    float qscale = (MODE == 0 && n0 == 0) ? 0.17677669529663687f : 1.0f;

    #pragma unroll
    for (int mt = 0; mt < 4; mt++) {
        int r0 = m0 + warp_m*64 + mt*16 + g;
        int r1 = r0 + 8;
        int t0 = r0, t1 = r1;
        if (MODE == 1) { t0 = win_to_token(r0, shift); t1 = win_to_token(r1, shift); }
        #pragma unroll
        for (int nt = 0; nt < 4; nt++) {
            int cb = n0 + warp_n*32 + nt*8 + 2*q;
            float bx = 0.f, by = 0.f;
            if (MODE != 4) { float2 bv = *(const float2*)(bias + cb); bx = bv.x; by = bv.y; }
            float v0 = c[mt][nt][0] + bx, v1 = c[mt][nt][1] + by;
            float v2 = c[mt][nt][2] + bx, v3 = c[mt][nt][3] + by;
            if (MODE == 0) {
                v0 *= qscale; v1 *= qscale; v2 *= qscale; v3 *= qscale;
                float2 o0 = {v0, v1}, o1 = {v2, v3};
                *(float2*)(out + (size_t)r0*N + cb) = o0;
                *(float2*)(out + (size_t)r1*N + cb) = o1;
            } else if (MODE == 1) {
                float2 rv0 = *(const float2*)(res + (size_t)t0*CC + cb);
                float2 rv1 = *(const float2*)(res + (size_t)t1*CC + cb);
                float2 o0 = {v0+rv0.x, v1+rv0.y}, o1 = {v2+rv1.x, v3+rv1.y};
                *(float2*)(out + (size_t)t0*CC + cb) = o0;
                *(float2*)(out + (size_t)t1*CC + cb) = o1;
            } else if (MODE == 2) {
                float2 o0, o1;
                o0.x = 0.5f*v0*(1.0f + erff(v0*0.7071067811865476f));
                o0.y = 0.5f*v1*(1.0f + erff(v1*0.7071067811865476f));
                o1.x = 0.5f*v2*(1.0f + erff(v2*0.7071067811865476f));
                o1.y = 0.5f*v3*(1.0f + erff(v3*0.7071067811865476f));
                *(float2*)(out + (size_t)r0*N + cb) = o0;
                *(float2*)(out + (size_t)r1*N + cb) = o1;
            } else if (MODE == 3) {
                float2 rv0 = *(const float2*)(res + (size_t)r0*N + cb);
                float2 rv1 = *(const float2*)(res + (size_t)r1*N + cb);
                float2 o0 = {v0+rv0.x, v1+rv0.y}, o1 = {v2+rv1.x, v3+rv1.y};
                *(float2*)(out + (size_t)r0*N + cb) = o0;
                *(float2*)(out + (size_t)r1*N + cb) = o1;
            } else {
                float2 o0 = {v0, v1}, o1 = {v2, v3};
                *(float2*)(out + (size_t)r0*N + cb) = o0;
                *(float2*)(out + (size_t)r1*N + cb) = o1;
            }
        }
    }
}

// ---------------- fused windowed attention: one (window, head) per block ----------------
__global__ void __launch_bounds__(128) attn_kernel(
    const float* __restrict__ qkv, float* __restrict__ out, int masked)
{
    __shared__ float qs[64][33];
    __shared__ float ks[64][32];
    __shared__ float vs[64][32];
    __shared__ float osm[64][32];
    __shared__ float red[2][64];
    __shared__ int lab[64];

    int tid = threadIdx.x;
    int win = blockIdx.x >> 2, head = blockIdx.x & 3;
    const float* base = qkv + (size_t)win*NTOK*384 + head*32;

    for (int i = tid; i < 512; i += 128) {
        int n = i >> 3, d4 = (i & 7) * 4;
        float4 q4 = *(const float4*)(base + (size_t)n*384 + d4);
        float4 k4 = *(const float4*)(base + (size_t)n*384 + 128 + d4);
        float4 v4 = *(const float4*)(base + (size_t)n*384 + 256 + d4);
        qs[n][d4+0] = q4.x; qs[n][d4+1] = q4.y; qs[n][d4+2] = q4.z; qs[n][d4+3] = q4.w;
        *(float4*)&ks[n][d4] = k4;
        *(float4*)&vs[n][d4] = v4;
    }
    if (masked && tid < 64) {
        int wloc = win % NWIN;
        int wr = wloc / 12, wc = wloc - wr*12;
        int hh = wr*8 + (tid >> 3), ww = wc*8 + (tid & 7);
        int rh = hh < 88 ? 0 : (hh < 92 ? 1 : 2);
        int rw = ww < 88 ? 0 : (ww < 92 ? 1 : 2);
        lab[tid] = rh*3 + rw;
    }
    __syncthreads();

    int r = tid & 63, ch = tid >> 6;
    float qreg[32];
    #pragma unroll
    for (int k = 0; k < 32; k++) qreg[k] = qs[r][k];

    float sreg[32];
    #pragma unroll
    for (int cc = 0; cc < 32; cc++) {
        int c = ch*32 + cc;
        float s = 0.0f;
        #pragma unroll
        for (int k = 0; k < 32; k++) s += qreg[k]*ks[c][k];
        sreg[cc] = s;
    }
    if (masked) {
        int lr = lab[r];
        float ninf = __int_as_float(0xff800000);
        #pragma unroll
        for (int cc = 0; cc < 32; cc++)
            if (lab[ch*32+cc] != lr) sreg[cc] = ninf;
    }
    float mx = sreg[0];
    #pragma unroll
    for (int cc = 1; cc < 32; cc++) mx = fmaxf(mx, sreg[cc]);
    red[ch][r] = mx; __syncthreads();
    mx = fmaxf(red[0][r], red[1][r]);
    __syncthreads();
    float sum = 0.0f;
    #pragma unroll
    for (int cc = 0; cc < 32; cc++) { sreg[cc] = __expf(sreg[cc]-mx); sum += sreg[cc]; }
    red[ch][r] = sum; __syncthreads();
    float inv = 1.0f/(red[0][r] + red[1][r]);
    #pragma unroll
    for (int cc = 0; cc < 32; cc++) sreg[cc] *= inv;

    float o[32];
    #pragma unroll
    for (int d = 0; d < 32; d++) o[d] = 0.0f;
    #pragma unroll
    for (int cc = 0; cc < 32; cc++) {
        int c = ch*32 + cc;
        float p = sreg[cc];
        #pragma unroll
        for (int d = 0; d < 32; d++) o[d] += p*vs[c][d];
    }
    if (ch == 1) {
        #pragma unroll
        for (int d = 0; d < 32; d++) osm[r][d] = o[d];
    }
    __syncthreads();
    if (ch == 0) {
        #pragma unroll
        for (int d = 0; d < 32; d++) osm[r][d] += o[d];
    }
    __syncthreads();

    float* orow = out + (size_t)win*NTOK*CC + head*32;
    for (int i = tid; i < 512; i += 128) {
        int n = i >> 3, d4 = (i & 7) * 4;
        *(float4*)(orow + (size_t)n*CC + d4) = *(float4*)&osm[n][d4];
    }
}

// ---------------- patch-merge gather + LN over 512 ----------------
__global__ void __launch_bounds__(128) merge_ln_kernel(
    const float* __restrict__ x, const float* __restrict__ g,
    const float* __restrict__ b, float* __restrict__ out)
{
    __shared__ float sred[8];
    int token = blockIdx.x;
    int b_ = token / 2304;
    int ij = token - b_*2304;
    int i2 = ij / 48, j2 = ij - (ij/48)*48;
    int tid = threadIdx.x;
    int warp = tid >> 5, lane = tid & 31;
    int chunk = tid >> 5;
    int cc = (tid & 31) * 4;
    int dh = chunk & 1, dw = chunk >> 1;
    int h = 2*i2 + dh, w = 2*j2 + dw;
    const float* src = x + ((size_t)(b_*(HH*WW) + h*WW + w))*CC + cc;
    float4 v = *(const float4*)src;

    float s = v.x + v.y + v.z + v.w;
    #pragma unroll
    for (int o = 16; o > 0; o >>= 1) s += __shfl_xor_sync(0xffffffffu, s, o);
    if (lane == 0) sred[warp] = s;
    __syncthreads();
    float m = (sred[0]+sred[1]+sred[2]+sred[3]) * (1.0f/512.0f);

    float dx = v.x-m, dy = v.y-m, dz = v.z-m, dwv = v.w-m;
    float q = dx*dx + dy*dy + dz*dz + dwv*dwv;
    #pragma unroll
    for (int o = 16; o > 0; o >>= 1) q += __shfl_xor_sync(0xffffffffu, q, o);
    if (lane == 0) sred[4+warp] = q;
    __syncthreads();
    float var = (sred[4]+sred[5]+sred[6]+sred[7]) * (1.0f/512.0f);
    float inv = rsqrtf(var + 1e-5f);

    int oc = tid*4;
    float4 gg = *(const float4*)(g + oc);
    float4 bb = *(const float4*)(b + oc);
    float4 r;
    r.x = dx*inv*gg.x + bb.x;
    r.y = dy*inv*gg.y + bb.y;
    r.z = dz*inv*gg.z + bb.z;
    r.w = dwv*inv*gg.w + bb.w;
    *(float4*)(out + (size_t)token*512 + oc) = r;
}

// ---------------- host orchestration ----------------
extern "C" void kernel_launch(void* const* d_in, const int* in_sizes, int n_in,
                              void* d_out, int out_size)
{
    (void)in_sizes; (void)n_in; (void)out_size;
    const float* P[28];
    for (int i = 0; i < 28; i++) P[i] = (const float*)d_in[i];
    const float* mln_g = P[25];
    const float* mln_b = P[26];
    const float* red_w = P[27];

    float *px, *pln, *pbig, *pattn, *pxc;
    cudaGetSymbolAddress((void**)&px,   g_x);
    cudaGetSymbolAddress((void**)&pln,  g_ln);
    cudaGetSymbolAddress((void**)&pbig, g_big);
    cudaGetSymbolAddress((void**)&pattn,g_attn);
    cudaGetSymbolAddress((void**)&pxc,  g_xc);

    static int smem_set = 0;
    if (!smem_set) {
        cudaFuncSetAttribute(tgemm<0>, cudaFuncAttributeMaxDynamicSharedMemorySize, GSMEM);
        cudaFuncSetAttribute(tgemm<1>, cudaFuncAttributeMaxDynamicSharedMemorySize, GSMEM);
        cudaFuncSetAttribute(tgemm<2>, cudaFuncAttributeMaxDynamicSharedMemorySize, GSMEM);
        cudaFuncSetAttribute(tgemm<3>, cudaFuncAttributeMaxDynamicSharedMemorySize, GSMEM);
        cudaFuncSetAttribute(tgemm<4>, cudaFuncAttributeMaxDynamicSharedMemorySize, GSMEM);
        smem_set = 1;
    }

    cudaMemcpyAsync(px, (const float*)d_in[0], (size_t)TT*CC*sizeof(float), cudaMemcpyDeviceToDevice);

    for (int blk = 0; blk < 2; blk++) {
        int base = 1 + blk*12;
        int shift  = (blk == 0) ? 0 : 4;
        int masked = (blk == 0) ? 0 : 1;

        ln_kernel<<<TT/8, 256>>>(px, P[base+0], P[base+1], pln, shift, 1);
        tgemm<0><<<dim3(3, TT/128), 256, GSMEM>>>(pln, P[base+2], P[base+3], pbig, nullptr, TT, 384, 128, 0);
        attn_kernel<<<WTOT*4, 128>>>(pbig, pattn, masked);
        tgemm<1><<<dim3(1, TT/128), 256, GSMEM>>>(pattn, P[base+4], P[base+5], px, px, TT, 128, 128, shift);
        ln_kernel<<<TT/8, 256>>>(px, P[base+6], P[base+7], pln, 0, 0);
        tgemm<2><<<dim3(4, TT/128), 256, GSMEM>>>(pln, P[base+8], P[base+9], pbig, nullptr, TT, 512, 128, 0);
        tgemm<3><<<dim3(1, TT/128), 256, GSMEM>>>(pbig, P[base+10], P[base+11], px, px, TT, 128, 512, 0);
    }

    merge_ln_kernel<<<TT/4, 128>>>(px, mln_g, mln_b, pxc);
    tgemm<4><<<dim3(2, (TT/4)/128), 256, GSMEM>>>(pxc, red_w, nullptr, (float*)d_out, nullptr, TT/4, 256, 512, 0);
}

// round 6
// speedup vs baseline: 2.0744x; 1.0089x over previous
#include <cuda_runtime.h>
#include <cuda_bf16.h>
#include <math.h>
#include <stdint.h>

// ---------------- problem constants ----------------
#define BB   8
#define HH   96
#define WW   96
#define CC   128
#define TT   (BB*HH*WW)      // 73728 tokens
#define NWIN 144             // 12*12 windows per image
#define WTOT (BB*NWIN)       // 1152 windows
#define NTOK 64              // tokens per window

// ---------------- scratch (device globals; no allocation) ----------------
__device__ float g_x[TT*CC];          // residual stream
__device__ float g_ln[TT*CC];         // LN output (window-ordered for ln1)
__device__ float g_big[TT*512];       // qkv (T x 384) / fc1-out (T x 512)
__device__ float g_attn[TT*CC];       // attention output (window-ordered)
__device__ float g_xc[(TT/4)*512];    // patch-merge concat + LN

// ---------------- helpers ----------------
__device__ __forceinline__ uint32_t smem_u32(const void* p) {
    uint32_t a;
    asm("{ .reg .u64 t; cvta.to.shared.u64 t, %1; cvt.u32.u64 %0, t; }" : "=r"(a) : "l"(p));
    return a;
}
__device__ __forceinline__ void cp16(uint32_t dst, const void* src) {
    asm volatile("cp.async.cg.shared.global [%0], [%1], 16;" :: "r"(dst), "l"(src));
}
__device__ __forceinline__ void cp_commit() {
    asm volatile("cp.async.commit_group;" ::: "memory");
}
template<int N>
__device__ __forceinline__ void cp_wait() {
    asm volatile("cp.async.wait_group %0;" :: "n"(N) : "memory");
}
__device__ __forceinline__ void mma_tf32(float* c, const uint32_t* a, const uint32_t* b) {
    asm volatile(
        "mma.sync.aligned.m16n8k8.row.col.f32.tf32.tf32.f32 "
        "{%0,%1,%2,%3}, {%4,%5,%6,%7}, {%8,%9}, {%0,%1,%2,%3};"
        : "+f"(c[0]), "+f"(c[1]), "+f"(c[2]), "+f"(c[3])
        : "r"(a[0]), "r"(a[1]), "r"(a[2]), "r"(a[3]), "r"(b[0]), "r"(b[1]));
}
__device__ __forceinline__ void ldsm4(uint32_t* r, uint32_t addr) {
    asm volatile("ldmatrix.sync.aligned.m8n8.x4.shared.b16 {%0,%1,%2,%3}, [%4];"
        : "=r"(r[0]), "=r"(r[1]), "=r"(r[2]), "=r"(r[3]) : "r"(addr));
}

__device__ __forceinline__ int win_to_token(int m, int shift) {
    int b   = m / (NWIN*NTOK);
    int rem = m - b*(NWIN*NTOK);
    int win = rem >> 6;
    int n   = rem & 63;
    int wr = win / 12, wc = win - wr*12;
    int hp = wr*8 + (n >> 3);
    int wp = wc*8 + (n & 7);
    int h = hp + shift; if (h >= HH) h -= HH;
    int w = wp + shift; if (w >= WW) w -= WW;
    return b*(HH*WW) + h*WW + w;
}

// ---------------- LN (warp per token), optional roll+window gather ----------------
__global__ void __launch_bounds__(256) ln_kernel(
    const float* __restrict__ x, const float* __restrict__ g,
    const float* __restrict__ b, float* __restrict__ out,
    int shift, int windowed)
{
    int warp = threadIdx.x >> 5;
    int lane = threadIdx.x & 31;
    int token = blockIdx.x*8 + warp;
    const float4* row = (const float4*)(x + (size_t)token*CC);
    float4 v = row[lane];
    float s = v.x + v.y + v.z + v.w;
    #pragma unroll
    for (int o = 16; o > 0; o >>= 1) s += __shfl_xor_sync(0xffffffffu, s, o);
    float m = s * (1.0f/128.0f);
    float dx = v.x - m, dy = v.y - m, dz = v.z - m, dw = v.w - m;
    float q = dx*dx + dy*dy + dz*dz + dw*dw;
    #pragma unroll
    for (int o = 16; o > 0; o >>= 1) q += __shfl_xor_sync(0xffffffffu, q, o);
    float inv = rsqrtf(q * (1.0f/128.0f) + 1e-5f);
    float4 gg = ((const float4*)g)[lane];
    float4 bb = ((const float4*)b)[lane];
    float4 r;
    r.x = dx*inv*gg.x + bb.x;
    r.y = dy*inv*gg.y + bb.y;
    r.z = dz*inv*gg.z + bb.z;
    r.w = dw*inv*gg.w + bb.w;
    int dest = token;
    if (windowed) {
        int bi = token / (HH*WW);
        int hw = token - bi*(HH*WW);
        int h = hw / WW, w = hw - (hw/WW)*WW;
        int hp = h - shift; if (hp < 0) hp += HH;
        int wp = w - shift; if (wp < 0) wp += WW;
        dest = bi*(NWIN*NTOK) + ((hp>>3)*12 + (wp>>3))*NTOK + ((hp&7)*8 + (wp&7));
    }
    ((float4*)(out + (size_t)dest*CC))[lane] = r;
}

// ---------------- mma.sync tf32 GEMM: D[M,N] = A[M,K] @ B[K,N], fused epilogues ----------------
// A smem: 128B rows (32 floats), XOR-swizzled 16B chunks (phys = chunk ^ (row&7)); ldmatrix feed.
// B smem: row-major [32][132] padded; scalar LDS feed.
// MODE 0: qkv (+bias, qscale on n0==0) 1: proj (+bias, scatter+res) 2: fc1 (+bias, GELU)
// MODE 3: fc2 (+bias, res)  4: plain
#define GBM 128
#define GBN 128
#define GBK 32
#define BSTR 132
#define AFLT (GBM*32)            // 4096 floats = 16KB
#define BFLT (GBK*BSTR)          // 4224 floats
#define STAGEF (AFLT+BFLT)       // 8320 floats
#define STAGEB (STAGEF*4)        // 33280 bytes
#define GSMEM (2*STAGEB)         // 66560 bytes

template<int MODE, int K>
__global__ void __launch_bounds__(256) tgemm(
    const float* __restrict__ A, const float* __restrict__ Bw,
    const float* __restrict__ bias, float* __restrict__ out,
    const float* __restrict__ res, int M, int N, int shift)
{
    extern __shared__ float sm[];
    uint32_t sb = smem_u32(sm);
    int tid = threadIdx.x;
    int wid = tid >> 5;
    int lane = tid & 31;
    int g = lane >> 2, q = lane & 3;
    int warp_m = wid >> 2, warp_n = wid & 3;  // 2 x 4
    int m0 = blockIdx.y * GBM, n0 = blockIdx.x * GBN;

    const float* Ab = A + (size_t)m0 * K;

    // loader indices
    int arow = tid >> 3;                       // 0..31 (+32 per iter)
    int achk = tid & 7;                        // 16B chunk within 128B row
    int brow = tid >> 5, bc4 = (tid & 31) * 4;

    // ldmatrix lane geometry
    int rowlane = lane & 15;                   // row offset within 16-row block
    int hiBit = lane >> 4;                     // 0: k-chunk +0, 1: +16B
    int lo7 = lane & 7;

    float c[4][4][4];
    #pragma unroll
    for (int mt = 0; mt < 4; mt++)
        #pragma unroll
        for (int nt = 0; nt < 4; nt++)
            #pragma unroll
            for (int i = 0; i < 4; i++) c[mt][nt][i] = 0.0f;

    const int NC = K / GBK;

    auto load_tile = [&](int kb) {
        int buf = kb & 1;
        uint32_t sA = sb + buf*STAGEB;
        uint32_t sB = sA + AFLT*4;
        const float* Ap = Ab + kb*GBK;
        const float* Bp = Bw + (size_t)(kb*GBK)*N + n0;
        #pragma unroll
        for (int i = 0; i < 4; i++) {
            int r = arow + i*32;
            cp16(sA + (uint32_t)(r*8 + (achk ^ (r & 7)))*16, Ap + (size_t)r*K + achk*4);
        }
        #pragma unroll
        for (int i = 0; i < 4; i++) {
            int r = brow + i*8;
            cp16(sB + (uint32_t)(r*BSTR + bc4)*4, Bp + (size_t)r*N + bc4);
        }
        cp_commit();
    };

    load_tile(0);

    #pragma unroll 2
    for (int kb = 0; kb < NC; kb++) {
        if (kb + 1 < NC) {
            load_tile(kb + 1);
            cp_wait<1>();
        } else {
            cp_wait<0>();
        }
        __syncthreads();

        int buf = kb & 1;
        uint32_t aBase = sb + buf*STAGEB + (uint32_t)(warp_m*64 + rowlane)*128;
        const float* Bs_ = sm + buf*STAGEF + AFLT;

        #pragma unroll
        for (int ks = 0; ks < 4; ks++) {
            uint32_t physOff = ((uint32_t)((ks*2 + hiBit) ^ lo7)) << 4;
            uint32_t a[4][4], b[4][2];
            #pragma unroll
            for (int mt = 0; mt < 4; mt++)
                ldsm4(a[mt], aBase + (uint32_t)mt*2048 + physOff);
            #pragma unroll
            for (int nt = 0; nt < 4; nt++) {
                int col = warp_n*32 + nt*8 + g;
                b[nt][0] = __float_as_uint(Bs_[(ks*8 + q)*BSTR + col]);
                b[nt][1] = __float_as_uint(Bs_[(ks*8 + q + 4)*BSTR + col]);
            }
            #pragma unroll
            for (int mt = 0; mt < 4; mt++)
                #pragma unroll
                for (int nt = 0; nt < 4; nt++)
                    mma_tf32(c[mt][nt], a[mt], b[nt]);
        }
        __syncthreads();
    }

    // ---- epilogue ----
    float qscale = (MODE == 0 && n0 == 0) ? 0.17677669529663687f : 1.0f;

    #pragma unroll
    for (int mt = 0; mt < 4; mt++) {
        int r0 = m0 + warp_m*64 + mt*16 + g;
        int r1 = r0 + 8;
        int t0 = r0, t1 = r1;
        if (MODE == 1) { t0 = win_to_token(r0, shift); t1 = win_to_token(r1, shift); }
        #pragma unroll
        for (int nt = 0; nt < 4; nt++) {
            int cb = n0 + warp_n*32 + nt*8 + 2*q;
            float bx = 0.f, by = 0.f;
            if (MODE != 4) { float2 bv = *(const float2*)(bias + cb); bx = bv.x; by = bv.y; }
            float v0 = c[mt][nt][0] + bx, v1 = c[mt][nt][1] + by;
            float v2 = c[mt][nt][2] + bx, v3 = c[mt][nt][3] + by;
            if (MODE == 0) {
                v0 *= qscale; v1 *= qscale; v2 *= qscale; v3 *= qscale;
                float2 o0 = {v0, v1}, o1 = {v2, v3};
                *(float2*)(out + (size_t)r0*N + cb) = o0;
                *(float2*)(out + (size_t)r1*N + cb) = o1;
            } else if (MODE == 1) {
                float2 rv0 = *(const float2*)(res + (size_t)t0*CC + cb);
                float2 rv1 = *(const float2*)(res + (size_t)t1*CC + cb);
                float2 o0 = {v0+rv0.x, v1+rv0.y}, o1 = {v2+rv1.x, v3+rv1.y};
                *(float2*)(out + (size_t)t0*CC + cb) = o0;
                *(float2*)(out + (size_t)t1*CC + cb) = o1;
            } else if (MODE == 2) {
                float2 o0, o1;
                o0.x = 0.5f*v0*(1.0f + erff(v0*0.7071067811865476f));
                o0.y = 0.5f*v1*(1.0f + erff(v1*0.7071067811865476f));
                o1.x = 0.5f*v2*(1.0f + erff(v2*0.7071067811865476f));
                o1.y = 0.5f*v3*(1.0f + erff(v3*0.7071067811865476f));
                *(float2*)(out + (size_t)r0*N + cb) = o0;
                *(float2*)(out + (size_t)r1*N + cb) = o1;
            } else if (MODE == 3) {
                float2 rv0 = *(const float2*)(res + (size_t)r0*N + cb);
                float2 rv1 = *(const float2*)(res + (size_t)r1*N + cb);
                float2 o0 = {v0+rv0.x, v1+rv0.y}, o1 = {v2+rv1.x, v3+rv1.y};
                *(float2*)(out + (size_t)r0*N + cb) = o0;
                *(float2*)(out + (size_t)r1*N + cb) = o1;
            } else {
                float2 o0 = {v0, v1}, o1 = {v2, v3};
                *(float2*)(out + (size_t)r0*N + cb) = o0;
                *(float2*)(out + (size_t)r1*N + cb) = o1;
            }
        }
    }
}

// ---------------- fused windowed attention: one (window, head) per block ----------------
__global__ void __launch_bounds__(128) attn_kernel(
    const float* __restrict__ qkv, float* __restrict__ out, int masked)
{
    __shared__ float qs[64][33];
    __shared__ float ks[64][32];
    __shared__ float vs[64][32];
    __shared__ float osm[64][32];
    __shared__ float red[2][64];
    __shared__ int lab[64];

    int tid = threadIdx.x;
    int win = blockIdx.x >> 2, head = blockIdx.x & 3;
    const float* base = qkv + (size_t)win*NTOK*384 + head*32;

    for (int i = tid; i < 512; i += 128) {
        int n = i >> 3, d4 = (i & 7) * 4;
        float4 q4 = *(const float4*)(base + (size_t)n*384 + d4);
        float4 k4 = *(const float4*)(base + (size_t)n*384 + 128 + d4);
        float4 v4 = *(const float4*)(base + (size_t)n*384 + 256 + d4);
        qs[n][d4+0] = q4.x; qs[n][d4+1] = q4.y; qs[n][d4+2] = q4.z; qs[n][d4+3] = q4.w;
        *(float4*)&ks[n][d4] = k4;
        *(float4*)&vs[n][d4] = v4;
    }
    if (masked && tid < 64) {
        int wloc = win % NWIN;
        int wr = wloc / 12, wc = wloc - wr*12;
        int hh = wr*8 + (tid >> 3), ww = wc*8 + (tid & 7);
        int rh = hh < 88 ? 0 : (hh < 92 ? 1 : 2);
        int rw = ww < 88 ? 0 : (ww < 92 ? 1 : 2);
        lab[tid] = rh*3 + rw;
    }
    __syncthreads();

    int r = tid & 63, ch = tid >> 6;
    float qreg[32];
    #pragma unroll
    for (int k = 0; k < 32; k++) qreg[k] = qs[r][k];

    float sreg[32];
    #pragma unroll
    for (int cc = 0; cc < 32; cc++) {
        int c = ch*32 + cc;
        float s = 0.0f;
        #pragma unroll
        for (int k = 0; k < 32; k++) s += qreg[k]*ks[c][k];
        sreg[cc] = s;
    }
    if (masked) {
        int lr = lab[r];
        float ninf = __int_as_float(0xff800000);
        #pragma unroll
        for (int cc = 0; cc < 32; cc++)
            if (lab[ch*32+cc] != lr) sreg[cc] = ninf;
    }
    float mx = sreg[0];
    #pragma unroll
    for (int cc = 1; cc < 32; cc++) mx = fmaxf(mx, sreg[cc]);
    red[ch][r] = mx; __syncthreads();
    mx = fmaxf(red[0][r], red[1][r]);
    __syncthreads();
    float sum = 0.0f;
    #pragma unroll
    for (int cc = 0; cc < 32; cc++) { sreg[cc] = __expf(sreg[cc]-mx); sum += sreg[cc]; }
    red[ch][r] = sum; __syncthreads();
    float inv = 1.0f/(red[0][r] + red[1][r]);
    #pragma unroll
    for (int cc = 0; cc < 32; cc++) sreg[cc] *= inv;

    float o[32];
    #pragma unroll
    for (int d = 0; d < 32; d++) o[d] = 0.0f;
    #pragma unroll
    for (int cc = 0; cc < 32; cc++) {
        int c = ch*32 + cc;
        float p = sreg[cc];
        #pragma unroll
        for (int d = 0; d < 32; d++) o[d] += p*vs[c][d];
    }
    if (ch == 1) {
        #pragma unroll
        for (int d = 0; d < 32; d++) osm[r][d] = o[d];
    }
    __syncthreads();
    if (ch == 0) {
        #pragma unroll
        for (int d = 0; d < 32; d++) osm[r][d] += o[d];
    }
    __syncthreads();

    float* orow = out + (size_t)win*NTOK*CC + head*32;
    for (int i = tid; i < 512; i += 128) {
        int n = i >> 3, d4 = (i & 7) * 4;
        *(float4*)(orow + (size_t)n*CC + d4) = *(float4*)&osm[n][d4];
    }
}

// ---------------- patch-merge gather + LN over 512 ----------------
__global__ void __launch_bounds__(128) merge_ln_kernel(
    const float* __restrict__ x, const float* __restrict__ g,
    const float* __restrict__ b, float* __restrict__ out)
{
    __shared__ float sred[8];
    int token = blockIdx.x;
    int b_ = token / 2304;
    int ij = token - b_*2304;
    int i2 = ij / 48, j2 = ij - (ij/48)*48;
    int tid = threadIdx.x;
    int warp = tid >> 5, lane = tid & 31;
    int chunk = tid >> 5;
    int cc = (tid & 31) * 4;
    int dh = chunk & 1, dw = chunk >> 1;
    int h = 2*i2 + dh, w = 2*j2 + dw;
    const float* src = x + ((size_t)(b_*(HH*WW) + h*WW + w))*CC + cc;
    float4 v = *(const float4*)src;

    float s = v.x + v.y + v.z + v.w;
    #pragma unroll
    for (int o = 16; o > 0; o >>= 1) s += __shfl_xor_sync(0xffffffffu, s, o);
    if (lane == 0) sred[warp] = s;
    __syncthreads();
    float m = (sred[0]+sred[1]+sred[2]+sred[3]) * (1.0f/512.0f);

    float dx = v.x-m, dy = v.y-m, dz = v.z-m, dwv = v.w-m;
    float q = dx*dx + dy*dy + dz*dz + dwv*dwv;
    #pragma unroll
    for (int o = 16; o > 0; o >>= 1) q += __shfl_xor_sync(0xffffffffu, q, o);
    if (lane == 0) sred[4+warp] = q;
    __syncthreads();
    float var = (sred[4]+sred[5]+sred[6]+sred[7]) * (1.0f/512.0f);
    float inv = rsqrtf(var + 1e-5f);

    int oc = tid*4;
    float4 gg = *(const float4*)(g + oc);
    float4 bb = *(const float4*)(b + oc);
    float4 r;
    r.x = dx*inv*gg.x + bb.x;
    r.y = dy*inv*gg.y + bb.y;
    r.z = dz*inv*gg.z + bb.z;
    r.w = dwv*inv*gg.w + bb.w;
    *(float4*)(out + (size_t)token*512 + oc) = r;
}

// ---------------- host orchestration ----------------
extern "C" void kernel_launch(void* const* d_in, const int* in_sizes, int n_in,
                              void* d_out, int out_size)
{
    (void)in_sizes; (void)n_in; (void)out_size;
    const float* P[28];
    for (int i = 0; i < 28; i++) P[i] = (const float*)d_in[i];
    const float* mln_g = P[25];
    const float* mln_b = P[26];
    const float* red_w = P[27];

    float *px, *pln, *pbig, *pattn, *pxc;
    cudaGetSymbolAddress((void**)&px,   g_x);
    cudaGetSymbolAddress((void**)&pln,  g_ln);
    cudaGetSymbolAddress((void**)&pbig, g_big);
    cudaGetSymbolAddress((void**)&pattn,g_attn);
    cudaGetSymbolAddress((void**)&pxc,  g_xc);

    static int smem_set = 0;
    if (!smem_set) {
        cudaFuncSetAttribute(tgemm<0,128>, cudaFuncAttributeMaxDynamicSharedMemorySize, GSMEM);
        cudaFuncSetAttribute(tgemm<1,128>, cudaFuncAttributeMaxDynamicSharedMemorySize, GSMEM);
        cudaFuncSetAttribute(tgemm<2,128>, cudaFuncAttributeMaxDynamicSharedMemorySize, GSMEM);
        cudaFuncSetAttribute(tgemm<3,512>, cudaFuncAttributeMaxDynamicSharedMemorySize, GSMEM);
        cudaFuncSetAttribute(tgemm<4,512>, cudaFuncAttributeMaxDynamicSharedMemorySize, GSMEM);
        smem_set = 1;
    }

    cudaMemcpyAsync(px, (const float*)d_in[0], (size_t)TT*CC*sizeof(float), cudaMemcpyDeviceToDevice);

    for (int blk = 0; blk < 2; blk++) {
        int base = 1 + blk*12;
        int shift  = (blk == 0) ? 0 : 4;
        int masked = (blk == 0) ? 0 : 1;

        ln_kernel<<<TT/8, 256>>>(px, P[base+0], P[base+1], pln, shift, 1);
        tgemm<0,128><<<dim3(3, TT/128), 256, GSMEM>>>(pln, P[base+2], P[base+3], pbig, nullptr, TT, 384, 0);
        attn_kernel<<<WTOT*4, 128>>>(pbig, pattn, masked);
        tgemm<1,128><<<dim3(1, TT/128), 256, GSMEM>>>(pattn, P[base+4], P[base+5], px, px, TT, 128, shift);
        ln_kernel<<<TT/8, 256>>>(px, P[base+6], P[base+7], pln, 0, 0);
        tgemm<2,128><<<dim3(4, TT/128), 256, GSMEM>>>(pln, P[base+8], P[base+9], pbig, nullptr, TT, 512, 0);
        tgemm<3,512><<<dim3(1, TT/128), 256, GSMEM>>>(pbig, P[base+10], P[base+11], px, px, TT, 128, 0);
    }

    merge_ln_kernel<<<TT/4, 128>>>(px, mln_g, mln_b, pxc);
    tgemm<4,512><<<dim3(2, (TT/4)/128), 256, GSMEM>>>(pxc, red_w, nullptr, (float*)d_out, nullptr, TT/4, 256, 0);
}

// round 7
// speedup vs baseline: 2.1990x; 1.0600x over previous
#include <cuda_runtime.h>
#include <cuda_bf16.h>
#include <math.h>
#include <stdint.h>

// ---------------- problem constants ----------------
#define BB   8
#define HH   96
#define WW   96
#define CC   128
#define TT   (BB*HH*WW)      // 73728 tokens
#define NWIN 144             // 12*12 windows per image
#define WTOT (BB*NWIN)       // 1152 windows
#define NTOK 64              // tokens per window

// ---------------- scratch (device globals; no allocation) ----------------
__device__ float g_x[TT*CC];          // residual stream
__device__ float g_ln[TT*CC];         // LN output (window-ordered for ln1)
__device__ float g_big[TT*512];       // qkv (T x 384) / fc1-out (T x 512)
__device__ float g_attn[TT*CC];       // attention output (window-ordered)
__device__ float g_xc[(TT/4)*512];    // patch-merge concat + LN

// ---------------- helpers ----------------
__device__ __forceinline__ uint32_t smem_u32(const void* p) {
    uint32_t a;
    asm("{ .reg .u64 t; cvta.to.shared.u64 t, %1; cvt.u32.u64 %0, t; }" : "=r"(a) : "l"(p));
    return a;
}
__device__ __forceinline__ void cp16(uint32_t dst, const void* src) {
    asm volatile("cp.async.cg.shared.global [%0], [%1], 16;" :: "r"(dst), "l"(src));
}
__device__ __forceinline__ void cp_commit() {
    asm volatile("cp.async.commit_group;" ::: "memory");
}
template<int N>
__device__ __forceinline__ void cp_wait() {
    asm volatile("cp.async.wait_group %0;" :: "n"(N) : "memory");
}
__device__ __forceinline__ void mma_tf32(float* c, const uint32_t* a, const uint32_t* b) {
    asm volatile(
        "mma.sync.aligned.m16n8k8.row.col.f32.tf32.tf32.f32 "
        "{%0,%1,%2,%3}, {%4,%5,%6,%7}, {%8,%9}, {%0,%1,%2,%3};"
        : "+f"(c[0]), "+f"(c[1]), "+f"(c[2]), "+f"(c[3])
        : "r"(a[0]), "r"(a[1]), "r"(a[2]), "r"(a[3]), "r"(b[0]), "r"(b[1]));
}
__device__ __forceinline__ void ldsm4(uint32_t* r, uint32_t addr) {
    asm volatile("ldmatrix.sync.aligned.m8n8.x4.shared.b16 {%0,%1,%2,%3}, [%4];"
        : "=r"(r[0]), "=r"(r[1]), "=r"(r[2]), "=r"(r[3]) : "r"(addr));
}

__device__ __forceinline__ int win_to_token(int m, int shift) {
    int b   = m / (NWIN*NTOK);
    int rem = m - b*(NWIN*NTOK);
    int win = rem >> 6;
    int n   = rem & 63;
    int wr = win / 12, wc = win - wr*12;
    int hp = wr*8 + (n >> 3);
    int wp = wc*8 + (n & 7);
    int h = hp + shift; if (h >= HH) h -= HH;
    int w = wp + shift; if (w >= WW) w -= WW;
    return b*(HH*WW) + h*WW + w;
}

// ---------------- LN (warp per token), optional roll+window gather + raw copy ----------------
__global__ void __launch_bounds__(256) ln_kernel(
    const float* __restrict__ x, const float* __restrict__ g,
    const float* __restrict__ b, float* __restrict__ out,
    float* __restrict__ xcopy, int shift, int windowed)
{
    int warp = threadIdx.x >> 5;
    int lane = threadIdx.x & 31;
    int token = blockIdx.x*8 + warp;
    const float4* row = (const float4*)(x + (size_t)token*CC);
    float4 v = row[lane];
    if (xcopy) ((float4*)(xcopy + (size_t)token*CC))[lane] = v;
    float s = v.x + v.y + v.z + v.w;
    #pragma unroll
    for (int o = 16; o > 0; o >>= 1) s += __shfl_xor_sync(0xffffffffu, s, o);
    float m = s * (1.0f/128.0f);
    float dx = v.x - m, dy = v.y - m, dz = v.z - m, dw = v.w - m;
    float q = dx*dx + dy*dy + dz*dz + dw*dw;
    #pragma unroll
    for (int o = 16; o > 0; o >>= 1) q += __shfl_xor_sync(0xffffffffu, q, o);
    float inv = rsqrtf(q * (1.0f/128.0f) + 1e-5f);
    float4 gg = ((const float4*)g)[lane];
    float4 bb = ((const float4*)b)[lane];
    float4 r;
    r.x = dx*inv*gg.x + bb.x;
    r.y = dy*inv*gg.y + bb.y;
    r.z = dz*inv*gg.z + bb.z;
    r.w = dw*inv*gg.w + bb.w;
    int dest = token;
    if (windowed) {
        int bi = token / (HH*WW);
        int hw = token - bi*(HH*WW);
        int h = hw / WW, w = hw - (hw/WW)*WW;
        int hp = h - shift; if (hp < 0) hp += HH;
        int wp = w - shift; if (wp < 0) wp += WW;
        dest = bi*(NWIN*NTOK) + ((hp>>3)*12 + (wp>>3))*NTOK + ((hp&7)*8 + (wp&7));
    }
    ((float4*)(out + (size_t)dest*CC))[lane] = r;
}

// ---------------- mma.sync tf32 GEMM: D[M,N] = A[M,K] @ B[K,N], fused epilogues ----------------
// A smem: 128B rows (32 floats), XOR-swizzled 16B chunks (phys = chunk ^ (row&7)); ldmatrix feed.
// B smem: row-major [32][132] padded; scalar LDS feed.
// 3-stage cp.async pipeline, one __syncthreads per k-iter.
// MODE 0: qkv (+bias, qscale on n0==0) 1: proj (+bias, scatter+res) 2: fc1 (+bias, GELU)
// MODE 3: fc2 (+bias, res)  4: plain
#define GBM 128
#define GBN 128
#define GBK 32
#define BSTR 132
#define AFLT (GBM*32)            // 4096 floats = 16KB
#define BFLT (GBK*BSTR)          // 4224 floats
#define STAGEF (AFLT+BFLT)       // 8320 floats
#define STAGEB (STAGEF*4)        // 33280 bytes
#define NSTAGE 3
#define GSMEM (NSTAGE*STAGEB)    // 99840 bytes

template<int MODE, int K>
__global__ void __launch_bounds__(256, 2) tgemm(
    const float* __restrict__ A, const float* __restrict__ Bw,
    const float* __restrict__ bias, float* __restrict__ out,
    const float* __restrict__ res, int M, int N, int shift)
{
    extern __shared__ float sm[];
    uint32_t sb = smem_u32(sm);
    int tid = threadIdx.x;
    int wid = tid >> 5;
    int lane = tid & 31;
    int g = lane >> 2, q = lane & 3;
    int warp_m = wid >> 2, warp_n = wid & 3;  // 2 x 4
    int m0 = blockIdx.y * GBM, n0 = blockIdx.x * GBN;

    const float* Ab = A + (size_t)m0 * K;

    // loader indices
    int arow = tid >> 3;                       // 0..31 (+32 per iter)
    int achk = tid & 7;                        // 16B chunk within 128B row
    int brow = tid >> 5, bc4 = (tid & 31) * 4;

    // ldmatrix lane geometry
    int rowlane = lane & 15;
    int hiBit = lane >> 4;
    int lo7 = lane & 7;

    float c[4][4][4];
    #pragma unroll
    for (int mt = 0; mt < 4; mt++)
        #pragma unroll
        for (int nt = 0; nt < 4; nt++)
            #pragma unroll
            for (int i = 0; i < 4; i++) c[mt][nt][i] = 0.0f;

    const int NC = K / GBK;

    auto load_tile = [&](int kb, int buf) {
        uint32_t sA = sb + buf*STAGEB;
        uint32_t sB = sA + AFLT*4;
        const float* Ap = Ab + kb*GBK;
        const float* Bp = Bw + (size_t)(kb*GBK)*N + n0;
        #pragma unroll
        for (int i = 0; i < 4; i++) {
            int r = arow + i*32;
            cp16(sA + (uint32_t)(r*8 + (achk ^ (r & 7)))*16, Ap + (size_t)r*K + achk*4);
        }
        #pragma unroll
        for (int i = 0; i < 4; i++) {
            int r = brow + i*8;
            cp16(sB + (uint32_t)(r*BSTR + bc4)*4, Bp + (size_t)r*N + bc4);
        }
        cp_commit();
    };

    load_tile(0, 0);
    if (NC > 1) load_tile(1, 1);

    int buf = 0;
    #pragma unroll 2
    for (int kb = 0; kb < NC; kb++) {
        cp_wait<NSTAGE-2>();
        __syncthreads();

        // prefetch kb+2 into buffer of kb-1 (safe: kb-1 compute finished before this sync)
        if (kb + 2 < NC) {
            int nbuf = buf + 2; if (nbuf >= NSTAGE) nbuf -= NSTAGE;
            load_tile(kb + 2, nbuf);
        }

        uint32_t aBase = sb + buf*STAGEB + (uint32_t)(warp_m*64 + rowlane)*128;
        const float* Bs_ = sm + buf*STAGEF + AFLT;

        #pragma unroll
        for (int ks = 0; ks < 4; ks++) {
            uint32_t physOff = ((uint32_t)((ks*2 + hiBit) ^ lo7)) << 4;
            uint32_t a[4][4], b[4][2];
            #pragma unroll
            for (int mt = 0; mt < 4; mt++)
                ldsm4(a[mt], aBase + (uint32_t)mt*2048 + physOff);
            #pragma unroll
            for (int nt = 0; nt < 4; nt++) {
                int col = warp_n*32 + nt*8 + g;
                b[nt][0] = __float_as_uint(Bs_[(ks*8 + q)*BSTR + col]);
                b[nt][1] = __float_as_uint(Bs_[(ks*8 + q + 4)*BSTR + col]);
            }
            #pragma unroll
            for (int mt = 0; mt < 4; mt++)
                #pragma unroll
                for (int nt = 0; nt < 4; nt++)
                    mma_tf32(c[mt][nt], a[mt], b[nt]);
        }
        buf++; if (buf >= NSTAGE) buf = 0;
    }

    // ---- epilogue ----
    float qscale = (MODE == 0 && n0 == 0) ? 0.17677669529663687f : 1.0f;

    #pragma unroll
    for (int mt = 0; mt < 4; mt++) {
        int r0 = m0 + warp_m*64 + mt*16 + g;
        int r1 = r0 + 8;
        int t0 = r0, t1 = r1;
        if (MODE == 1) { t0 = win_to_token(r0, shift); t1 = win_to_token(r1, shift); }
        #pragma unroll
        for (int nt = 0; nt < 4; nt++) {
            int cb = n0 + warp_n*32 + nt*8 + 2*q;
            float bx = 0.f, by = 0.f;
            if (MODE != 4) { float2 bv = *(const float2*)(bias + cb); bx = bv.x; by = bv.y; }
            float v0 = c[mt][nt][0] + bx, v1 = c[mt][nt][1] + by;
            float v2 = c[mt][nt][2] + bx, v3 = c[mt][nt][3] + by;
            if (MODE == 0) {
                v0 *= qscale; v1 *= qscale; v2 *= qscale; v3 *= qscale;
                float2 o0 = {v0, v1}, o1 = {v2, v3};
                *(float2*)(out + (size_t)r0*N + cb) = o0;
                *(float2*)(out + (size_t)r1*N + cb) = o1;
            } else if (MODE == 1) {
                float2 rv0 = *(const float2*)(res + (size_t)t0*CC + cb);
                float2 rv1 = *(const float2*)(res + (size_t)t1*CC + cb);
                float2 o0 = {v0+rv0.x, v1+rv0.y}, o1 = {v2+rv1.x, v3+rv1.y};
                *(float2*)(out + (size_t)t0*CC + cb) = o0;
                *(float2*)(out + (size_t)t1*CC + cb) = o1;
            } else if (MODE == 2) {
                float2 o0, o1;
                o0.x = 0.5f*v0*(1.0f + erff(v0*0.7071067811865476f));
                o0.y = 0.5f*v1*(1.0f + erff(v1*0.7071067811865476f));
                o1.x = 0.5f*v2*(1.0f + erff(v2*0.7071067811865476f));
                o1.y = 0.5f*v3*(1.0f + erff(v3*0.7071067811865476f));
                *(float2*)(out + (size_t)r0*N + cb) = o0;
                *(float2*)(out + (size_t)r1*N + cb) = o1;
            } else if (MODE == 3) {
                float2 rv0 = *(const float2*)(res + (size_t)r0*N + cb);
                float2 rv1 = *(const float2*)(res + (size_t)r1*N + cb);
                float2 o0 = {v0+rv0.x, v1+rv0.y}, o1 = {v2+rv1.x, v3+rv1.y};
                *(float2*)(out + (size_t)r0*N + cb) = o0;
                *(float2*)(out + (size_t)r1*N + cb) = o1;
            } else {
                float2 o0 = {v0, v1}, o1 = {v2, v3};
                *(float2*)(out + (size_t)r0*N + cb) = o0;
                *(float2*)(out + (size_t)r1*N + cb) = o1;
            }
        }
    }
}

// ---------------- fused windowed attention: one (window, head) per block ----------------
__global__ void __launch_bounds__(128) attn_kernel(
    const float* __restrict__ qkv, float* __restrict__ out, int masked)
{
    __shared__ float qs[64][33];
    __shared__ float ks[64][32];
    __shared__ float vs[64][32];
    __shared__ float osm[64][32];
    __shared__ float red[2][64];
    __shared__ int lab[64];

    int tid = threadIdx.x;
    int win = blockIdx.x >> 2, head = blockIdx.x & 3;
    const float* base = qkv + (size_t)win*NTOK*384 + head*32;

    for (int i = tid; i < 512; i += 128) {
        int n = i >> 3, d4 = (i & 7) * 4;
        float4 q4 = *(const float4*)(base + (size_t)n*384 + d4);
        float4 k4 = *(const float4*)(base + (size_t)n*384 + 128 + d4);
        float4 v4 = *(const float4*)(base + (size_t)n*384 + 256 + d4);
        qs[n][d4+0] = q4.x; qs[n][d4+1] = q4.y; qs[n][d4+2] = q4.z; qs[n][d4+3] = q4.w;
        *(float4*)&ks[n][d4] = k4;
        *(float4*)&vs[n][d4] = v4;
    }
    if (masked && tid < 64) {
        int wloc = win % NWIN;
        int wr = wloc / 12, wc = wloc - wr*12;
        int hh = wr*8 + (tid >> 3), ww = wc*8 + (tid & 7);
        int rh = hh < 88 ? 0 : (hh < 92 ? 1 : 2);
        int rw = ww < 88 ? 0 : (ww < 92 ? 1 : 2);
        lab[tid] = rh*3 + rw;
    }
    __syncthreads();

    int r = tid & 63, ch = tid >> 6;
    float qreg[32];
    #pragma unroll
    for (int k = 0; k < 32; k++) qreg[k] = qs[r][k];

    float sreg[32];
    #pragma unroll
    for (int cc = 0; cc < 32; cc++) {
        int c = ch*32 + cc;
        float s = 0.0f;
        #pragma unroll
        for (int k = 0; k < 32; k++) s += qreg[k]*ks[c][k];
        sreg[cc] = s;
    }
    if (masked) {
        int lr = lab[r];
        float ninf = __int_as_float(0xff800000);
        #pragma unroll
        for (int cc = 0; cc < 32; cc++)
            if (lab[ch*32+cc] != lr) sreg[cc] = ninf;
    }
    float mx = sreg[0];
    #pragma unroll
    for (int cc = 1; cc < 32; cc++) mx = fmaxf(mx, sreg[cc]);
    red[ch][r] = mx; __syncthreads();
    mx = fmaxf(red[0][r], red[1][r]);
    __syncthreads();
    float sum = 0.0f;
    #pragma unroll
    for (int cc = 0; cc < 32; cc++) { sreg[cc] = __expf(sreg[cc]-mx); sum += sreg[cc]; }
    red[ch][r] = sum; __syncthreads();
    float inv = 1.0f/(red[0][r] + red[1][r]);
    #pragma unroll
    for (int cc = 0; cc < 32; cc++) sreg[cc] *= inv;

    float o[32];
    #pragma unroll
    for (int d = 0; d < 32; d++) o[d] = 0.0f;
    #pragma unroll
    for (int cc = 0; cc < 32; cc++) {
        int c = ch*32 + cc;
        float p = sreg[cc];
        #pragma unroll
        for (int d = 0; d < 32; d++) o[d] += p*vs[c][d];
    }
    if (ch == 1) {
        #pragma unroll
        for (int d = 0; d < 32; d++) osm[r][d] = o[d];
    }
    __syncthreads();
    if (ch == 0) {
        #pragma unroll
        for (int d = 0; d < 32; d++) osm[r][d] += o[d];
    }
    __syncthreads();

    float* orow = out + (size_t)win*NTOK*CC + head*32;
    for (int i = tid; i < 512; i += 128) {
        int n = i >> 3, d4 = (i & 7) * 4;
        *(float4*)(orow + (size_t)n*CC + d4) = *(float4*)&osm[n][d4];
    }
}

// ---------------- patch-merge gather + LN over 512 ----------------
__global__ void __launch_bounds__(128) merge_ln_kernel(
    const float* __restrict__ x, const float* __restrict__ g,
    const float* __restrict__ b, float* __restrict__ out)
{
    __shared__ float sred[8];
    int token = blockIdx.x;
    int b_ = token / 2304;
    int ij = token - b_*2304;
    int i2 = ij / 48, j2 = ij - (ij/48)*48;
    int tid = threadIdx.x;
    int warp = tid >> 5, lane = tid & 31;
    int chunk = tid >> 5;
    int cc = (tid & 31) * 4;
    int dh = chunk & 1, dw = chunk >> 1;
    int h = 2*i2 + dh, w = 2*j2 + dw;
    const float* src = x + ((size_t)(b_*(HH*WW) + h*WW + w))*CC + cc;
    float4 v = *(const float4*)src;

    float s = v.x + v.y + v.z + v.w;
    #pragma unroll
    for (int o = 16; o > 0; o >>= 1) s += __shfl_xor_sync(0xffffffffu, s, o);
    if (lane == 0) sred[warp] = s;
    __syncthreads();
    float m = (sred[0]+sred[1]+sred[2]+sred[3]) * (1.0f/512.0f);

    float dx = v.x-m, dy = v.y-m, dz = v.z-m, dwv = v.w-m;
    float q = dx*dx + dy*dy + dz*dz + dwv*dwv;
    #pragma unroll
    for (int o = 16; o > 0; o >>= 1) q += __shfl_xor_sync(0xffffffffu, q, o);
    if (lane == 0) sred[4+warp] = q;
    __syncthreads();
    float var = (sred[4]+sred[5]+sred[6]+sred[7]) * (1.0f/512.0f);
    float inv = rsqrtf(var + 1e-5f);

    int oc = tid*4;
    float4 gg = *(const float4*)(g + oc);
    float4 bb = *(const float4*)(b + oc);
    float4 r;
    r.x = dx*inv*gg.x + bb.x;
    r.y = dy*inv*gg.y + bb.y;
    r.z = dz*inv*gg.z + bb.z;
    r.w = dwv*inv*gg.w + bb.w;
    *(float4*)(out + (size_t)token*512 + oc) = r;
}

// ---------------- host orchestration ----------------
extern "C" void kernel_launch(void* const* d_in, const int* in_sizes, int n_in,
                              void* d_out, int out_size)
{
    (void)in_sizes; (void)n_in; (void)out_size;
    const float* P[28];
    for (int i = 0; i < 28; i++) P[i] = (const float*)d_in[i];
    const float* mln_g = P[25];
    const float* mln_b = P[26];
    const float* red_w = P[27];

    float *px, *pln, *pbig, *pattn, *pxc;
    cudaGetSymbolAddress((void**)&px,   g_x);
    cudaGetSymbolAddress((void**)&pln,  g_ln);
    cudaGetSymbolAddress((void**)&pbig, g_big);
    cudaGetSymbolAddress((void**)&pattn,g_attn);
    cudaGetSymbolAddress((void**)&pxc,  g_xc);

    static int smem_set = 0;
    if (!smem_set) {
        cudaFuncSetAttribute(tgemm<0,128>, cudaFuncAttributeMaxDynamicSharedMemorySize, GSMEM);
        cudaFuncSetAttribute(tgemm<1,128>, cudaFuncAttributeMaxDynamicSharedMemorySize, GSMEM);
        cudaFuncSetAttribute(tgemm<2,128>, cudaFuncAttributeMaxDynamicSharedMemorySize, GSMEM);
        cudaFuncSetAttribute(tgemm<3,512>, cudaFuncAttributeMaxDynamicSharedMemorySize, GSMEM);
        cudaFuncSetAttribute(tgemm<4,512>, cudaFuncAttributeMaxDynamicSharedMemorySize, GSMEM);
        smem_set = 1;
    }

    for (int blk = 0; blk < 2; blk++) {
        int base = 1 + blk*12;
        int shift  = (blk == 0) ? 0 : 4;
        int masked = (blk == 0) ? 0 : 1;
        const float* lnsrc = (blk == 0) ? (const float*)d_in[0] : px;
        float* xcopy = (blk == 0) ? px : nullptr;

        ln_kernel<<<TT/8, 256>>>(lnsrc, P[base+0], P[base+1], pln, xcopy, shift, 1);
        tgemm<0,128><<<dim3(3, TT/128), 256, GSMEM>>>(pln, P[base+2], P[base+3], pbig, nullptr, TT, 384, 0);
        attn_kernel<<<WTOT*4, 128>>>(pbig, pattn, masked);
        tgemm<1,128><<<dim3(1, TT/128), 256, GSMEM>>>(pattn, P[base+4], P[base+5], px, px, TT, 128, shift);
        ln_kernel<<<TT/8, 256>>>(px, P[base+6], P[base+7], pln, nullptr, 0, 0);
        tgemm<2,128><<<dim3(4, TT/128), 256, GSMEM>>>(pln, P[base+8], P[base+9], pbig, nullptr, TT, 512, 0);
        tgemm<3,512><<<dim3(1, TT/128), 256, GSMEM>>>(pbig, P[base+10], P[base+11], px, px, TT, 128, 0);
    }

    merge_ln_kernel<<<TT/4, 128>>>(px, mln_g, mln_b, pxc);
    tgemm<4,512><<<dim3(2, (TT/4)/128), 256, GSMEM>>>(pxc, red_w, nullptr, (float*)d_out, nullptr, TT/4, 256, 0);
}

// round 8
// speedup vs baseline: 2.2228x; 1.0108x over previous
#include <cuda_runtime.h>
#include <cuda_bf16.h>
#include <math.h>
#include <stdint.h>

// ---------------- problem constants ----------------
#define BB   8
#define HH   96
#define WW   96
#define CC   128
#define TT   (BB*HH*WW)      // 73728 tokens
#define NWIN 144             // 12*12 windows per image
#define WTOT (BB*NWIN)       // 1152 windows
#define NTOK 64              // tokens per window

// ---------------- scratch (device globals; no allocation) ----------------
__device__ float g_x[TT*CC];          // residual stream
__device__ float g_ln[TT*CC];         // LN output (window-ordered for ln1)
__device__ float g_big[TT*512];       // qkv (T x 384) / fc1-out (T x 512)
__device__ float g_attn[TT*CC];       // attention output (window-ordered)
__device__ float g_xc[(TT/4)*512];    // patch-merge concat + LN

// ---------------- helpers ----------------
__device__ __forceinline__ uint32_t smem_u32(const void* p) {
    uint32_t a;
    asm("{ .reg .u64 t; cvta.to.shared.u64 t, %1; cvt.u32.u64 %0, t; }" : "=r"(a) : "l"(p));
    return a;
}
__device__ __forceinline__ void cp16(uint32_t dst, const void* src) {
    asm volatile("cp.async.cg.shared.global [%0], [%1], 16;" :: "r"(dst), "l"(src));
}
__device__ __forceinline__ void cp_commit() {
    asm volatile("cp.async.commit_group;" ::: "memory");
}
template<int N>
__device__ __forceinline__ void cp_wait() {
    asm volatile("cp.async.wait_group %0;" :: "n"(N) : "memory");
}
__device__ __forceinline__ void mma_tf32(float* c, const uint32_t* a, const uint32_t* b) {
    asm volatile(
        "mma.sync.aligned.m16n8k8.row.col.f32.tf32.tf32.f32 "
        "{%0,%1,%2,%3}, {%4,%5,%6,%7}, {%8,%9}, {%0,%1,%2,%3};"
        : "+f"(c[0]), "+f"(c[1]), "+f"(c[2]), "+f"(c[3])
        : "r"(a[0]), "r"(a[1]), "r"(a[2]), "r"(a[3]), "r"(b[0]), "r"(b[1]));
}
__device__ __forceinline__ void ldsm4(uint32_t* r, uint32_t addr) {
    asm volatile("ldmatrix.sync.aligned.m8n8.x4.shared.b16 {%0,%1,%2,%3}, [%4];"
        : "=r"(r[0]), "=r"(r[1]), "=r"(r[2]), "=r"(r[3]) : "r"(addr));
}

// window-ordered row -> natural token (reverse roll by +shift)
__device__ __forceinline__ int win_to_token(int m, int shift) {
    int b   = m / (NWIN*NTOK);
    int rem = m - b*(NWIN*NTOK);
    int win = rem >> 6;
    int n   = rem & 63;
    int wr = win / 12, wc = win - wr*12;
    int hp = wr*8 + (n >> 3);
    int wp = wc*8 + (n & 7);
    int h = hp + shift; if (h >= HH) h -= HH;
    int w = wp + shift; if (w >= WW) w -= WW;
    return b*(HH*WW) + h*WW + w;
}
// natural token -> window-ordered index (forward roll by -shift)
__device__ __forceinline__ int tok_to_win(int t, int shift) {
    int bi = t / (HH*WW);
    int hw = t - bi*(HH*WW);
    int h = hw / WW, w = hw - (hw/WW)*WW;
    int hp = h - shift; if (hp < 0) hp += HH;
    int wp = w - shift; if (wp < 0) wp += WW;
    return bi*(NWIN*NTOK) + ((hp>>3)*12 + (wp>>3))*NTOK + ((hp&7)*8 + (wp&7));
}

// ---------------- LN (warp per token), optional roll+window gather + raw copy ----------------
__global__ void __launch_bounds__(256) ln_kernel(
    const float* __restrict__ x, const float* __restrict__ g,
    const float* __restrict__ b, float* __restrict__ out,
    float* __restrict__ xcopy, int shift, int windowed)
{
    int warp = threadIdx.x >> 5;
    int lane = threadIdx.x & 31;
    int token = blockIdx.x*8 + warp;
    const float4* row = (const float4*)(x + (size_t)token*CC);
    float4 v = row[lane];
    if (xcopy) ((float4*)(xcopy + (size_t)token*CC))[lane] = v;
    float s = v.x + v.y + v.z + v.w;
    #pragma unroll
    for (int o = 16; o > 0; o >>= 1) s += __shfl_xor_sync(0xffffffffu, s, o);
    float m = s * (1.0f/128.0f);
    float dx = v.x - m, dy = v.y - m, dz = v.z - m, dw = v.w - m;
    float q = dx*dx + dy*dy + dz*dz + dw*dw;
    #pragma unroll
    for (int o = 16; o > 0; o >>= 1) q += __shfl_xor_sync(0xffffffffu, q, o);
    float inv = rsqrtf(q * (1.0f/128.0f) + 1e-5f);
    float4 gg = ((const float4*)g)[lane];
    float4 bb = ((const float4*)b)[lane];
    float4 r;
    r.x = dx*inv*gg.x + bb.x;
    r.y = dy*inv*gg.y + bb.y;
    r.z = dz*inv*gg.z + bb.z;
    r.w = dw*inv*gg.w + bb.w;
    int dest = token;
    if (windowed) dest = tok_to_win(token, shift);
    ((float4*)(out + (size_t)dest*CC))[lane] = r;
}

// ---------------- mma.sync tf32 GEMM: D[M,N] = A[M,K] @ B[K,N], fused epilogues ----------------
// MODE 0: qkv (+bias, qscale on n0==0) 1: proj (+bias, scatter+res) 2: fc1 (+bias, GELU)
// MODE 3: fc2 (+bias, res)  4: plain
// LNF (only MODE 1/3, requires N=128, gridx=1): 0 none; 1 also write LN(x) at natural token;
//     2 also write LN(x) window-gathered with `shift` (next block's ln1).
#define GBM 128
#define GBN 128
#define GBK 32
#define BSTR 132
#define AFLT (GBM*32)            // 4096 floats = 16KB
#define BFLT (GBK*BSTR)          // 4224 floats
#define STAGEF (AFLT+BFLT)       // 8320 floats
#define STAGEB (STAGEF*4)        // 33280 bytes
#define NSTAGE 3
#define GSMEM (NSTAGE*STAGEB)    // 99840 bytes

template<int MODE, int K, int LNF>
__global__ void __launch_bounds__(256, 2) tgemm(
    const float* __restrict__ A, const float* __restrict__ Bw,
    const float* __restrict__ bias, float* __restrict__ out,
    const float* __restrict__ res,
    const float* __restrict__ lng, const float* __restrict__ lnb,
    float* __restrict__ lnout,
    int M, int N, int shift)
{
    extern __shared__ float sm[];
    uint32_t sb = smem_u32(sm);
    int tid = threadIdx.x;
    int wid = tid >> 5;
    int lane = tid & 31;
    int g = lane >> 2, q = lane & 3;
    int warp_m = wid >> 2, warp_n = wid & 3;  // 2 x 4
    int m0 = blockIdx.y * GBM, n0 = blockIdx.x * GBN;

    const float* Ab = A + (size_t)m0 * K;

    int arow = tid >> 3;
    int achk = tid & 7;
    int brow = tid >> 5, bc4 = (tid & 31) * 4;

    int rowlane = lane & 15;
    int hiBit = lane >> 4;
    int lo7 = lane & 7;

    float c[4][4][4];
    #pragma unroll
    for (int mt = 0; mt < 4; mt++)
        #pragma unroll
        for (int nt = 0; nt < 4; nt++)
            #pragma unroll
            for (int i = 0; i < 4; i++) c[mt][nt][i] = 0.0f;

    const int NC = K / GBK;

    auto load_tile = [&](int kb, int buf) {
        uint32_t sA = sb + buf*STAGEB;
        uint32_t sB = sA + AFLT*4;
        const float* Ap = Ab + kb*GBK;
        const float* Bp = Bw + (size_t)(kb*GBK)*N + n0;
        #pragma unroll
        for (int i = 0; i < 4; i++) {
            int r = arow + i*32;
            cp16(sA + (uint32_t)(r*8 + (achk ^ (r & 7)))*16, Ap + (size_t)r*K + achk*4);
        }
        #pragma unroll
        for (int i = 0; i < 4; i++) {
            int r = brow + i*8;
            cp16(sB + (uint32_t)(r*BSTR + bc4)*4, Bp + (size_t)r*N + bc4);
        }
        cp_commit();
    };

    load_tile(0, 0);
    if (NC > 1) load_tile(1, 1);

    int buf = 0;
    #pragma unroll 2
    for (int kb = 0; kb < NC; kb++) {
        if (kb == NC - 1) cp_wait<0>(); else cp_wait<NSTAGE-2>();
        __syncthreads();

        if (kb + 2 < NC) {
            int nbuf = buf + 2; if (nbuf >= NSTAGE) nbuf -= NSTAGE;
            load_tile(kb + 2, nbuf);
        }

        uint32_t aBase = sb + buf*STAGEB + (uint32_t)(warp_m*64 + rowlane)*128;
        const float* Bs_ = sm + buf*STAGEF + AFLT;

        #pragma unroll
        for (int ks = 0; ks < 4; ks++) {
            uint32_t physOff = ((uint32_t)((ks*2 + hiBit) ^ lo7)) << 4;
            uint32_t a[4][4], b[4][2];
            #pragma unroll
            for (int mt = 0; mt < 4; mt++)
                ldsm4(a[mt], aBase + (uint32_t)mt*2048 + physOff);
            #pragma unroll
            for (int nt = 0; nt < 4; nt++) {
                int col = warp_n*32 + nt*8 + g;
                b[nt][0] = __float_as_uint(Bs_[(ks*8 + q)*BSTR + col]);
                b[nt][1] = __float_as_uint(Bs_[(ks*8 + q + 4)*BSTR + col]);
            }
            #pragma unroll
            for (int mt = 0; mt < 4; mt++)
                #pragma unroll
                for (int nt = 0; nt < 4; nt++)
                    mma_tf32(c[mt][nt], a[mt], b[nt]);
        }
        buf++; if (buf >= NSTAGE) buf = 0;
    }

    if (LNF == 0) {
        // ---- plain epilogue ----
        float qscale = (MODE == 0 && n0 == 0) ? 0.17677669529663687f : 1.0f;
        #pragma unroll
        for (int mt = 0; mt < 4; mt++) {
            int r0 = m0 + warp_m*64 + mt*16 + g;
            int r1 = r0 + 8;
            int t0 = r0, t1 = r1;
            if (MODE == 1) { t0 = win_to_token(r0, shift); t1 = win_to_token(r1, shift); }
            #pragma unroll
            for (int nt = 0; nt < 4; nt++) {
                int cb = n0 + warp_n*32 + nt*8 + 2*q;
                float bx = 0.f, by = 0.f;
                if (MODE != 4) { float2 bv = *(const float2*)(bias + cb); bx = bv.x; by = bv.y; }
                float v0 = c[mt][nt][0] + bx, v1 = c[mt][nt][1] + by;
                float v2 = c[mt][nt][2] + bx, v3 = c[mt][nt][3] + by;
                if (MODE == 0) {
                    v0 *= qscale; v1 *= qscale; v2 *= qscale; v3 *= qscale;
                    float2 o0 = {v0, v1}, o1 = {v2, v3};
                    *(float2*)(out + (size_t)r0*N + cb) = o0;
                    *(float2*)(out + (size_t)r1*N + cb) = o1;
                } else if (MODE == 1) {
                    float2 rv0 = *(const float2*)(res + (size_t)t0*CC + cb);
                    float2 rv1 = *(const float2*)(res + (size_t)t1*CC + cb);
                    float2 o0 = {v0+rv0.x, v1+rv0.y}, o1 = {v2+rv1.x, v3+rv1.y};
                    *(float2*)(out + (size_t)t0*CC + cb) = o0;
                    *(float2*)(out + (size_t)t1*CC + cb) = o1;
                } else if (MODE == 2) {
                    float2 o0, o1;
                    o0.x = 0.5f*v0*(1.0f + erff(v0*0.7071067811865476f));
                    o0.y = 0.5f*v1*(1.0f + erff(v1*0.7071067811865476f));
                    o1.x = 0.5f*v2*(1.0f + erff(v2*0.7071067811865476f));
                    o1.y = 0.5f*v3*(1.0f + erff(v3*0.7071067811865476f));
                    *(float2*)(out + (size_t)r0*N + cb) = o0;
                    *(float2*)(out + (size_t)r1*N + cb) = o1;
                } else if (MODE == 3) {
                    float2 rv0 = *(const float2*)(res + (size_t)r0*N + cb);
                    float2 rv1 = *(const float2*)(res + (size_t)r1*N + cb);
                    float2 o0 = {v0+rv0.x, v1+rv0.y}, o1 = {v2+rv1.x, v3+rv1.y};
                    *(float2*)(out + (size_t)r0*N + cb) = o0;
                    *(float2*)(out + (size_t)r1*N + cb) = o1;
                } else {
                    float2 o0 = {v0, v1}, o1 = {v2, v3};
                    *(float2*)(out + (size_t)r0*N + cb) = o0;
                    *(float2*)(out + (size_t)r1*N + cb) = o1;
                }
            }
        }
    } else {
        // ---- LN-fused epilogue (MODE 1 or 3; N == 128, n0 == 0) ----
        // phase 0: fold bias + residual into c, accumulate per-row sum/sumsq
        int tok[4][2];
        float rs[4][2], rq[4][2];
        #pragma unroll
        for (int mt = 0; mt < 4; mt++) {
            int r0 = m0 + warp_m*64 + mt*16 + g;
            int r1 = r0 + 8;
            int t0 = (MODE == 1) ? win_to_token(r0, shift) : r0;
            int t1 = (MODE == 1) ? win_to_token(r1, shift) : r1;
            tok[mt][0] = t0; tok[mt][1] = t1;
            float s0 = 0.f, s1 = 0.f, q0 = 0.f, q1 = 0.f;
            #pragma unroll
            for (int nt = 0; nt < 4; nt++) {
                int cb = warp_n*32 + nt*8 + 2*q;
                float2 bv = *(const float2*)(bias + cb);
                float2 rv0 = *(const float2*)(res + (size_t)t0*CC + cb);
                float2 rv1 = *(const float2*)(res + (size_t)t1*CC + cb);
                float v0 = c[mt][nt][0] + bv.x + rv0.x;
                float v1 = c[mt][nt][1] + bv.y + rv0.y;
                float v2 = c[mt][nt][2] + bv.x + rv1.x;
                float v3 = c[mt][nt][3] + bv.y + rv1.y;
                c[mt][nt][0] = v0; c[mt][nt][1] = v1;
                c[mt][nt][2] = v2; c[mt][nt][3] = v3;
                s0 += v0 + v1; q0 += v0*v0 + v1*v1;
                s1 += v2 + v3; q1 += v2*v2 + v3*v3;
            }
            s0 += __shfl_xor_sync(0xffffffffu, s0, 1); s0 += __shfl_xor_sync(0xffffffffu, s0, 2);
            q0 += __shfl_xor_sync(0xffffffffu, q0, 1); q0 += __shfl_xor_sync(0xffffffffu, q0, 2);
            s1 += __shfl_xor_sync(0xffffffffu, s1, 1); s1 += __shfl_xor_sync(0xffffffffu, s1, 2);
            q1 += __shfl_xor_sync(0xffffffffu, q1, 1); q1 += __shfl_xor_sync(0xffffffffu, q1, 2);
            rs[mt][0] = s0; rq[mt][0] = q0;
            rs[mt][1] = s1; rq[mt][1] = q1;
        }
        __syncthreads();   // all warps done with pipeline smem before reuse
        float* ps = sm;           // [4][128]
        float* pq = sm + 512;     // [4][128]
        if (q == 0) {
            #pragma unroll
            for (int mt = 0; mt < 4; mt++) {
                int lr0 = warp_m*64 + mt*16 + g;
                ps[warp_n*128 + lr0] = rs[mt][0];
                pq[warp_n*128 + lr0] = rq[mt][0];
                ps[warp_n*128 + lr0 + 8] = rs[mt][1];
                pq[warp_n*128 + lr0 + 8] = rq[mt][1];
            }
        }
        __syncthreads();
        #pragma unroll
        for (int mt = 0; mt < 4; mt++) {
            #pragma unroll
            for (int half = 0; half < 2; half++) {
                int lr = warp_m*64 + mt*16 + g + half*8;
                int t = tok[mt][half];
                float srow = ps[lr] + ps[128 + lr] + ps[256 + lr] + ps[384 + lr];
                float qrow = pq[lr] + pq[128 + lr] + pq[256 + lr] + pq[384 + lr];
                float mean = srow * (1.0f/128.0f);
                float var = qrow * (1.0f/128.0f) - mean*mean;
                float inv = rsqrtf(var + 1e-5f);
                int dest = (LNF == 1) ? t : tok_to_win(t, shift);
                #pragma unroll
                for (int nt = 0; nt < 4; nt++) {
                    int cb = warp_n*32 + nt*8 + 2*q;
                    float v0 = c[mt][nt][half*2+0];
                    float v1 = c[mt][nt][half*2+1];
                    float2 o = {v0, v1};
                    *(float2*)(out + (size_t)t*CC + cb) = o;
                    float2 lg = *(const float2*)(lng + cb);
                    float2 lb = *(const float2*)(lnb + cb);
                    float2 l;
                    l.x = (v0 - mean)*inv*lg.x + lb.x;
                    l.y = (v1 - mean)*inv*lg.y + lb.y;
                    *(float2*)(lnout + (size_t)dest*CC + cb) = l;
                }
            }
        }
    }
}

// ---------------- fused windowed attention: one (window, head) per block ----------------
__global__ void __launch_bounds__(128) attn_kernel(
    const float* __restrict__ qkv, float* __restrict__ out, int masked)
{
    __shared__ float qs[64][33];
    __shared__ float ks[64][32];
    __shared__ float vs[64][32];
    __shared__ float osm[64][32];
    __shared__ float red[2][64];
    __shared__ int lab[64];

    int tid = threadIdx.x;
    int win = blockIdx.x >> 2, head = blockIdx.x & 3;
    const float* base = qkv + (size_t)win*NTOK*384 + head*32;

    for (int i = tid; i < 512; i += 128) {
        int n = i >> 3, d4 = (i & 7) * 4;
        float4 q4 = *(const float4*)(base + (size_t)n*384 + d4);
        float4 k4 = *(const float4*)(base + (size_t)n*384 + 128 + d4);
        float4 v4 = *(const float4*)(base + (size_t)n*384 + 256 + d4);
        qs[n][d4+0] = q4.x; qs[n][d4+1] = q4.y; qs[n][d4+2] = q4.z; qs[n][d4+3] = q4.w;
        *(float4*)&ks[n][d4] = k4;
        *(float4*)&vs[n][d4] = v4;
    }
    if (masked && tid < 64) {
        int wloc = win % NWIN;
        int wr = wloc / 12, wc = wloc - wr*12;
        int hh = wr*8 + (tid >> 3), ww = wc*8 + (tid & 7);
        int rh = hh < 88 ? 0 : (hh < 92 ? 1 : 2);
        int rw = ww < 88 ? 0 : (ww < 92 ? 1 : 2);
        lab[tid] = rh*3 + rw;
    }
    __syncthreads();

    int r = tid & 63, ch = tid >> 6;
    float qreg[32];
    #pragma unroll
    for (int k = 0; k < 32; k++) qreg[k] = qs[r][k];

    float sreg[32];
    #pragma unroll
    for (int cc = 0; cc < 32; cc++) {
        int c = ch*32 + cc;
        float s = 0.0f;
        #pragma unroll
        for (int k = 0; k < 32; k++) s += qreg[k]*ks[c][k];
        sreg[cc] = s;
    }
    if (masked) {
        int lr = lab[r];
        float ninf = __int_as_float(0xff800000);
        #pragma unroll
        for (int cc = 0; cc < 32; cc++)
            if (lab[ch*32+cc] != lr) sreg[cc] = ninf;
    }
    float mx = sreg[0];
    #pragma unroll
    for (int cc = 1; cc < 32; cc++) mx = fmaxf(mx, sreg[cc]);
    red[ch][r] = mx; __syncthreads();
    mx = fmaxf(red[0][r], red[1][r]);
    __syncthreads();
    float sum = 0.0f;
    #pragma unroll
    for (int cc = 0; cc < 32; cc++) { sreg[cc] = __expf(sreg[cc]-mx); sum += sreg[cc]; }
    red[ch][r] = sum; __syncthreads();
    float inv = 1.0f/(red[0][r] + red[1][r]);
    #pragma unroll
    for (int cc = 0; cc < 32; cc++) sreg[cc] *= inv;

    float o[32];
    #pragma unroll
    for (int d = 0; d < 32; d++) o[d] = 0.0f;
    #pragma unroll
    for (int cc = 0; cc < 32; cc++) {
        int c = ch*32 + cc;
        float p = sreg[cc];
        #pragma unroll
        for (int d = 0; d < 32; d++) o[d] += p*vs[c][d];
    }
    if (ch == 1) {
        #pragma unroll
        for (int d = 0; d < 32; d++) osm[r][d] = o[d];
    }
    __syncthreads();
    if (ch == 0) {
        #pragma unroll
        for (int d = 0; d < 32; d++) osm[r][d] += o[d];
    }
    __syncthreads();

    float* orow = out + (size_t)win*NTOK*CC + head*32;
    for (int i = tid; i < 512; i += 128) {
        int n = i >> 3, d4 = (i & 7) * 4;
        *(float4*)(orow + (size_t)n*CC + d4) = *(float4*)&osm[n][d4];
    }
}

// ---------------- patch-merge gather + LN over 512 ----------------
__global__ void __launch_bounds__(128) merge_ln_kernel(
    const float* __restrict__ x, const float* __restrict__ g,
    const float* __restrict__ b, float* __restrict__ out)
{
    __shared__ float sred[8];
    int token = blockIdx.x;
    int b_ = token / 2304;
    int ij = token - b_*2304;
    int i2 = ij / 48, j2 = ij - (ij/48)*48;
    int tid = threadIdx.x;
    int warp = tid >> 5, lane = tid & 31;
    int chunk = tid >> 5;
    int cc = (tid & 31) * 4;
    int dh = chunk & 1, dw = chunk >> 1;
    int h = 2*i2 + dh, w = 2*j2 + dw;
    const float* src = x + ((size_t)(b_*(HH*WW) + h*WW + w))*CC + cc;
    float4 v = *(const float4*)src;

    float s = v.x + v.y + v.z + v.w;
    #pragma unroll
    for (int o = 16; o > 0; o >>= 1) s += __shfl_xor_sync(0xffffffffu, s, o);
    if (lane == 0) sred[warp] = s;
    __syncthreads();
    float m = (sred[0]+sred[1]+sred[2]+sred[3]) * (1.0f/512.0f);

    float dx = v.x-m, dy = v.y-m, dz = v.z-m, dwv = v.w-m;
    float q = dx*dx + dy*dy + dz*dz + dwv*dwv;
    #pragma unroll
    for (int o = 16; o > 0; o >>= 1) q += __shfl_xor_sync(0xffffffffu, q, o);
    if (lane == 0) sred[4+warp] = q;
    __syncthreads();
    float var = (sred[4]+sred[5]+sred[6]+sred[7]) * (1.0f/512.0f);
    float inv = rsqrtf(var + 1e-5f);

    int oc = tid*4;
    float4 gg = *(const float4*)(g + oc);
    float4 bb = *(const float4*)(b + oc);
    float4 r;
    r.x = dx*inv*gg.x + bb.x;
    r.y = dy*inv*gg.y + bb.y;
    r.z = dz*inv*gg.z + bb.z;
    r.w = dwv*inv*gg.w + bb.w;
    *(float4*)(out + (size_t)token*512 + oc) = r;
}

// ---------------- host orchestration ----------------
extern "C" void kernel_launch(void* const* d_in, const int* in_sizes, int n_in,
                              void* d_out, int out_size)
{
    (void)in_sizes; (void)n_in; (void)out_size;
    const float* P[28];
    for (int i = 0; i < 28; i++) P[i] = (const float*)d_in[i];
    const float* mln_g = P[25];
    const float* mln_b = P[26];
    const float* red_w = P[27];

    float *px, *pln, *pbig, *pattn, *pxc;
    cudaGetSymbolAddress((void**)&px,   g_x);
    cudaGetSymbolAddress((void**)&pln,  g_ln);
    cudaGetSymbolAddress((void**)&pbig, g_big);
    cudaGetSymbolAddress((void**)&pattn,g_attn);
    cudaGetSymbolAddress((void**)&pxc,  g_xc);

    static int smem_set = 0;
    if (!smem_set) {
        cudaFuncSetAttribute(tgemm<0,128,0>, cudaFuncAttributeMaxDynamicSharedMemorySize, GSMEM);
        cudaFuncSetAttribute(tgemm<1,128,1>, cudaFuncAttributeMaxDynamicSharedMemorySize, GSMEM);
        cudaFuncSetAttribute(tgemm<2,128,0>, cudaFuncAttributeMaxDynamicSharedMemorySize, GSMEM);
        cudaFuncSetAttribute(tgemm<3,512,2>, cudaFuncAttributeMaxDynamicSharedMemorySize, GSMEM);
        cudaFuncSetAttribute(tgemm<3,512,0>, cudaFuncAttributeMaxDynamicSharedMemorySize, GSMEM);
        cudaFuncSetAttribute(tgemm<4,512,0>, cudaFuncAttributeMaxDynamicSharedMemorySize, GSMEM);
        smem_set = 1;
    }

    // ---- block 0 (W-MSA, shift 0) ----
    ln_kernel<<<TT/8, 256>>>((const float*)d_in[0], P[1], P[2], pln, px, 0, 1);
    tgemm<0,128,0><<<dim3(3, TT/128), 256, GSMEM>>>(pln, P[3], P[4], pbig, nullptr, nullptr, nullptr, nullptr, TT, 384, 0);
    attn_kernel<<<WTOT*4, 128>>>(pbig, pattn, 0);
    // proj + residual + ln2(a) fused
    tgemm<1,128,1><<<dim3(1, TT/128), 256, GSMEM>>>(pattn, P[5], P[6], px, px, P[7], P[8], pln, TT, 128, 0);
    tgemm<2,128,0><<<dim3(4, TT/128), 256, GSMEM>>>(pln, P[9], P[10], pbig, nullptr, nullptr, nullptr, nullptr, TT, 512, 0);
    // fc2 + residual + ln1(b) + window-gather(shift 4) fused
    tgemm<3,512,2><<<dim3(1, TT/128), 256, GSMEM>>>(pbig, P[11], P[12], px, px, P[13], P[14], pln, TT, 128, 4);

    // ---- block 1 (SW-MSA, shift 4) ----
    tgemm<0,128,0><<<dim3(3, TT/128), 256, GSMEM>>>(pln, P[15], P[16], pbig, nullptr, nullptr, nullptr, nullptr, TT, 384, 0);
    attn_kernel<<<WTOT*4, 128>>>(pbig, pattn, 1);
    tgemm<1,128,1><<<dim3(1, TT/128), 256, GSMEM>>>(pattn, P[17], P[18], px, px, P[19], P[20], pln, TT, 128, 4);
    tgemm<2,128,0><<<dim3(4, TT/128), 256, GSMEM>>>(pln, P[21], P[22], pbig, nullptr, nullptr, nullptr, nullptr, TT, 512, 0);
    tgemm<3,512,0><<<dim3(1, TT/128), 256, GSMEM>>>(pbig, P[23], P[24], px, px, nullptr, nullptr, nullptr, TT, 128, 0);

    merge_ln_kernel<<<TT/4, 128>>>(px, mln_g, mln_b, pxc);
    tgemm<4,512,0><<<dim3(2, (TT/4)/128), 256, GSMEM>>>(pxc, red_w, nullptr, (float*)d_out, nullptr, nullptr, nullptr, nullptr, TT/4, 256, 0);
}